// round 11
// baseline (speedup 1.0000x reference)
#include <cuda_runtime.h>
#include <cuda_bf16.h>
#include <cstdint>

// Problem constants
#define BATCH 4
#define SEQ   2048
#define FDIM  512
#define EDIM  512
#define HEADS 8
#define DH    64
#define MROWS (BATCH*SEQ)      // 8192

// tcgen05 only exists in arch-accelerated ('a') compilation passes.
#if defined(__CUDA_ARCH_FEAT_SM103_ALL) || defined(__CUDA_ARCH_FEAT_SM100_ALL) || \
    defined(__CUDA_ARCH_SPECIFIC__) || defined(__CUDA_ARCH_FAMILY_SPECIFIC__)
#define TC_ENABLED 1
#else
#define TC_ENABLED 0
#endif

// Scratch: Q/K in [B,H,S,DH]; V stored TRANSPOSED [B,H,DH,S] for the PV MMA.
__device__ float g_q[(size_t)BATCH*HEADS*SEQ*DH];
__device__ float g_k[(size_t)BATCH*HEADS*SEQ*DH];
__device__ float g_v[(size_t)BATCH*HEADS*DH*SEQ];
// W^T concat [1536 n][512 k] fp32 (Wq^T | Wk^T | Wv^T), written by cvt_wt.
__device__ float g_wt[(size_t)3*EDIM*FDIM];

// ===========================================================================
// PTX helpers
// ===========================================================================
__device__ __forceinline__ uint32_t smem_u32(const void* p) {
    uint32_t a;
    asm("{ .reg .u64 t; cvta.to.shared.u64 t, %1; cvt.u32.u64 %0, t; }" : "=r"(a) : "l"(p));
    return a;
}
__device__ __forceinline__ bool elect_one() {
    uint32_t pred;
    asm volatile("{\n\t.reg .pred p;\n\telect.sync _|p, 0xFFFFFFFF;\n\t"
                 "selp.b32 %0, 1, 0, p;\n\t}" : "=r"(pred));
    return pred != 0;
}
__device__ __forceinline__ float rna_tf32(float x) {
    uint32_t u;
    asm("cvt.rna.tf32.f32 %0, %1;" : "=r"(u) : "f"(x));
    return __uint_as_float(u);
}
__device__ __forceinline__ uint32_t rna_tf32_bits(float x) {
    uint32_t u;
    asm("cvt.rna.tf32.f32 %0, %1;" : "=r"(u) : "f"(x));
    return u;
}
// bf16 hi/lo split of a pair (a=low half, b=high half)
__device__ __forceinline__ void bf16_split2(float a, float b, uint32_t& h, uint32_t& l) {
    __nv_bfloat16 ha = __float2bfloat16(a), hb = __float2bfloat16(b);
    float ra = a - __bfloat162float(ha);
    float rb = b - __bfloat162float(hb);
    __nv_bfloat16 la = __float2bfloat16(ra), lb = __float2bfloat16(rb);
    h = ((uint32_t)__bfloat16_as_ushort(hb) << 16) | __bfloat16_as_ushort(ha);
    l = ((uint32_t)__bfloat16_as_ushort(lb) << 16) | __bfloat16_as_ushort(la);
}

#define TC_ALLOC(smem_addr, n) \
    asm volatile("tcgen05.alloc.cta_group::1.sync.aligned.shared::cta.b32 [%0], %1;" \
                 :: "r"(smem_addr), "r"((uint32_t)(n)) : "memory")
#define TC_RELINQ() \
    asm volatile("tcgen05.relinquish_alloc_permit.cta_group::1.sync.aligned;")
#define TC_DEALLOC(tmem_addr, n) \
    asm volatile("tcgen05.dealloc.cta_group::1.sync.aligned.b32 %0, %1;" \
                 :: "r"(tmem_addr), "r"((uint32_t)(n)))
#define TC_WAIT_ST() asm volatile("tcgen05.wait::st.sync.aligned;" ::: "memory")
#define TC_WAIT_LD() asm volatile("tcgen05.wait::ld.sync.aligned;" ::: "memory")
#define TC_FENCE_BEFORE() asm volatile("tcgen05.fence::before_thread_sync;" ::: "memory")
#define TC_FENCE_AFTER()  asm volatile("tcgen05.fence::after_thread_sync;" ::: "memory")
#define TC_COMMIT(mbar) \
    asm volatile("tcgen05.commit.cta_group::1.mbarrier::arrive::one.shared::cluster.b64 [%0];" \
                 :: "r"((uint32_t)(mbar)) : "memory")

#define TC_ST_X32(tmem_addr, r) \
    asm volatile("tcgen05.st.sync.aligned.32x32b.x32.b32 [%0], " \
        "{%1, %2, %3, %4, %5, %6, %7, %8, %9, %10, %11, %12, %13, %14, %15, %16, " \
        " %17, %18, %19, %20, %21, %22, %23, %24, %25, %26, %27, %28, %29, %30, %31, %32};" \
        :: "r"(tmem_addr), \
           "r"((r)[0]),"r"((r)[1]),"r"((r)[2]),"r"((r)[3]),"r"((r)[4]),"r"((r)[5]),"r"((r)[6]),"r"((r)[7]), \
           "r"((r)[8]),"r"((r)[9]),"r"((r)[10]),"r"((r)[11]),"r"((r)[12]),"r"((r)[13]),"r"((r)[14]),"r"((r)[15]), \
           "r"((r)[16]),"r"((r)[17]),"r"((r)[18]),"r"((r)[19]),"r"((r)[20]),"r"((r)[21]),"r"((r)[22]),"r"((r)[23]), \
           "r"((r)[24]),"r"((r)[25]),"r"((r)[26]),"r"((r)[27]),"r"((r)[28]),"r"((r)[29]),"r"((r)[30]),"r"((r)[31]) \
        : "memory")

#define TC_ST_X16(tmem_addr, r) \
    asm volatile("tcgen05.st.sync.aligned.32x32b.x16.b32 [%0], " \
        "{%1, %2, %3, %4, %5, %6, %7, %8, %9, %10, %11, %12, %13, %14, %15, %16};" \
        :: "r"(tmem_addr), \
           "r"((r)[0]),"r"((r)[1]),"r"((r)[2]),"r"((r)[3]),"r"((r)[4]),"r"((r)[5]),"r"((r)[6]),"r"((r)[7]), \
           "r"((r)[8]),"r"((r)[9]),"r"((r)[10]),"r"((r)[11]),"r"((r)[12]),"r"((r)[13]),"r"((r)[14]),"r"((r)[15]) \
        : "memory")

#define TC_LD_X32(r, tmem_addr) \
    asm volatile("tcgen05.ld.sync.aligned.32x32b.x32.b32 " \
        "{%0, %1, %2, %3, %4, %5, %6, %7, %8, %9, %10, %11, %12, %13, %14, %15, " \
        " %16, %17, %18, %19, %20, %21, %22, %23, %24, %25, %26, %27, %28, %29, %30, %31}, [%32];" \
        : "=r"((r)[0]),"=r"((r)[1]),"=r"((r)[2]),"=r"((r)[3]),"=r"((r)[4]),"=r"((r)[5]),"=r"((r)[6]),"=r"((r)[7]), \
          "=r"((r)[8]),"=r"((r)[9]),"=r"((r)[10]),"=r"((r)[11]),"=r"((r)[12]),"=r"((r)[13]),"=r"((r)[14]),"=r"((r)[15]), \
          "=r"((r)[16]),"=r"((r)[17]),"=r"((r)[18]),"=r"((r)[19]),"=r"((r)[20]),"=r"((r)[21]),"=r"((r)[22]),"=r"((r)[23]), \
          "=r"((r)[24]),"=r"((r)[25]),"=r"((r)[26]),"=r"((r)[27]),"=r"((r)[28]),"=r"((r)[29]),"=r"((r)[30]),"=r"((r)[31]) \
        : "r"(tmem_addr))

#define MBAR_INIT(mbar, cnt) \
    asm volatile("mbarrier.init.shared.b64 [%0], %1;" :: "r"((uint32_t)(mbar)), "r"((uint32_t)(cnt)) : "memory")

#define MBAR_WAIT(mbar, parity) do { \
    uint32_t _m = (uint32_t)(mbar); uint32_t _p = (uint32_t)(parity); uint32_t _done; \
    asm volatile("{\n\t.reg .pred p;\n\t" \
        "mbarrier.try_wait.parity.acquire.cta.shared::cta.b64 p, [%1], %2;\n\t" \
        "selp.b32 %0, 1, 0, p;\n\t}" : "=r"(_done) : "r"(_m), "r"(_p) : "memory"); \
    if (!_done) { \
        asm volatile("{\n\t.reg .pred P1;\n\t" \
            "WAIT_LOOP_%=:\n\t" \
            "mbarrier.try_wait.parity.acquire.cta.shared::cta.b64 P1, [%0], %1, 0x989680;\n\t" \
            "@P1 bra.uni WAIT_DONE_%=;\n\t" \
            "bra.uni WAIT_LOOP_%=;\n\t" \
            "WAIT_DONE_%=:\n\t}" :: "r"(_m), "r"(_p) : "memory"); \
    } \
} while (0)

// SW128 SMEM descriptor (layout=2, version=1, SBO=64, LBO=1)
#define SMEM_DESC_BASE_SW128 \
    ((uint64_t(2) << 61) | (uint64_t(1) << 46) | (uint64_t(64) << 32) | (uint64_t(1) << 16))
#define MKDESC(addr) (SMEM_DESC_BASE_SW128 | ((uint64_t)((addr) >> 4) & 0x3FFF))
#define SWZ128(o) ((o) ^ (((o) >> 3) & 0x70))

#if TC_ENABLED
__device__ __forceinline__ void mma_tf32_ts(uint32_t d, uint32_t a, uint64_t bdesc,
                                            uint32_t idesc, bool acc) {
    uint32_t e = acc ? 1u : 0u;
    asm volatile("{\n\t.reg .pred p;\n\tsetp.ne.u32 p, %4, 0;\n\t"
        "tcgen05.mma.cta_group::1.kind::tf32 [%0], [%1], %2, %3, p;\n\t}"
        :: "r"(d), "r"(a), "l"(bdesc), "r"(idesc), "r"(e) : "memory");
}
__device__ __forceinline__ void mma_f16_ts(uint32_t d, uint32_t a, uint64_t bdesc,
                                           uint32_t idesc, bool acc) {
    uint32_t e = acc ? 1u : 0u;
    asm volatile("{\n\t.reg .pred p;\n\tsetp.ne.u32 p, %5, 0;\n\t"
        "tcgen05.mma.cta_group::1.kind::f16 [%0], [%1], %2, %3, {%4, %4, %4, %4}, p;\n\t}"
        :: "r"(d), "r"(a), "l"(bdesc), "r"(idesc), "r"(0u), "r"(e) : "memory");
}
#endif

// tf32 idesc (GEMM, proven): M=128, N=64
#define IDESC_A ((1u<<4)|(2u<<7)|(2u<<10)|((64u/8)<<17)|((128u/16)<<24))
// bf16 idescs (attention, round-10 layout-validated)
#define IDESC_BS  ((1u<<4)|(1u<<7)|(1u<<10)|((128u/8)<<17)|((128u/16)<<24))  // S: N=128
#define IDESC_BPV ((1u<<4)|(1u<<7)|(1u<<10)|((64u/8)<<17)|((128u/16)<<24))   // PV: N=64

// ===========================================================================
// cvt_wt (proven, unchanged)
// ===========================================================================
__global__ __launch_bounds__(256)
void cvt_wt(const float* __restrict__ Wq, const float* __restrict__ Wk,
            const float* __restrict__ Wv)
{
    __shared__ float t[32][33];
    const int z = blockIdx.z;
    const float* W = (z == 0) ? Wq : (z == 1) ? Wk : Wv;
    const int k0 = blockIdx.x * 32;
    const int n0 = blockIdx.y * 32;
    const int tx = threadIdx.x & 31;
    const int ty = threadIdx.x >> 5;
    #pragma unroll
    for (int i = 0; i < 4; i++)
        t[ty + 8*i][tx] = W[(size_t)(k0 + ty + 8*i) * EDIM + n0 + tx];
    __syncthreads();
    #pragma unroll
    for (int i = 0; i < 4; i++)
        g_wt[(size_t)(z * EDIM + n0 + ty + 8*i) * FDIM + k0 + tx] = t[tx][ty + 8*i];
}

// ===========================================================================
// tcgen05 tf32x3 projection GEMM (round-8 PROVEN, unchanged).
// ===========================================================================
#define TXH 0
#define TXL 64
#define TD  128
#define GT_TMEMPTR 0
#define GT_MBAR    16
#define GT_BIAS    64
#define GT_WH0     1024
#define GT_WH1     (GT_WH0 + 8192)
#define GT_WL0     (GT_WH1 + 8192)
#define GT_WL1     (GT_WL0 + 8192)
#define GT_TOTAL   (GT_WL1 + 8192)     // 33792

__global__ __launch_bounds__(128)
void tc_gemm(const float* __restrict__ x,
             const float* __restrict__ etype,
             const float* __restrict__ bq, const float* __restrict__ bk,
             const float* __restrict__ bv)
{
    extern __shared__ char sm[];
    const int tid = threadIdx.x;
    const int m0 = blockIdx.x * 128;
    const int n0g = blockIdx.y * 64;
    const int which = n0g >> 9;
    const int e0 = n0g & 511;
    const int hh = e0 >> 6;
    const float* bias = (which == 0) ? bq : (which == 1) ? bk : bv;

#if TC_ENABLED
    const uint32_t base = smem_u32(sm);
    const int wid = tid >> 5;
    const uint32_t warpoff = (uint32_t)wid << 21;

    if (wid == 0) { TC_ALLOC(base + GT_TMEMPTR, 256); TC_RELINQ(); }
    __syncthreads();
    uint32_t tmem;
    asm volatile("ld.shared.b32 %0, [%1];" : "=r"(tmem) : "r"(base + GT_TMEMPTR));
    if (tid == 0) MBAR_INIT(base + GT_MBAR, 1);
    if (tid < 64) ((float*)(sm + GT_BIAS))[tid] = bias[e0 + tid];
    __syncthreads();

    const uint64_t dWH0 = MKDESC(base + GT_WH0);
    const uint64_t dWH1 = MKDESC(base + GT_WH1);
    const uint64_t dWL0 = MKDESC(base + GT_WL0);
    const uint64_t dWL1 = MKDESC(base + GT_WL1);

    for (int c = 0; c < 8; c++) {
        const int k0 = c * 64;
        #pragma unroll
        for (int i = 0; i < 8; i++) {
            int idx = tid + i * 128;
            int r = idx >> 4, c4 = idx & 15;
            float4 v = *(const float4*)&g_wt[(size_t)(n0g + r) * FDIM + k0 + c4 * 4];
            float4 hi, lo;
            hi.x = rna_tf32(v.x); lo.x = rna_tf32(v.x - hi.x);
            hi.y = rna_tf32(v.y); lo.y = rna_tf32(v.y - hi.y);
            hi.z = rna_tf32(v.z); lo.z = rna_tf32(v.z - hi.z);
            hi.w = rna_tf32(v.w); lo.w = rna_tf32(v.w - hi.w);
            uint32_t o = SWZ128((uint32_t)(r * 128 + (c4 & 7) * 16));
            uint32_t bh_off = (c4 & 8) ? GT_WH1 : GT_WH0;
            uint32_t bl_off = (c4 & 8) ? GT_WL1 : GT_WL0;
            *(float4*)(sm + bh_off + o) = hi;
            *(float4*)(sm + bl_off + o) = lo;
        }
        {
            const float4* xp = (const float4*)(x + (size_t)(m0 + tid) * FDIM + k0);
            uint32_t rh[64], rl[64];
            #pragma unroll
            for (int i = 0; i < 16; i++) {
                float4 v = xp[i];
                float f[4] = { v.x, v.y, v.z, v.w };
                #pragma unroll
                for (int cc = 0; cc < 4; cc++) {
                    float hi = rna_tf32(f[cc]);
                    rh[i*4+cc] = __float_as_uint(hi);
                    rl[i*4+cc] = rna_tf32_bits(f[cc] - hi);
                }
            }
            TC_ST_X32(tmem + TXH + warpoff, rh);
            TC_ST_X32(tmem + TXH + 32 + warpoff, rh + 32);
            TC_ST_X32(tmem + TXL + warpoff, rl);
            TC_ST_X32(tmem + TXL + 32 + warpoff, rl + 32);
            TC_WAIT_ST();
        }
        TC_FENCE_BEFORE();
        __syncthreads();

        if (wid == 0) {
            TC_FENCE_AFTER();
            if (elect_one()) {
                #pragma unroll
                for (int s = 0; s < 8; s++) {
                    uint64_t bh_d = (s < 4) ? (dWH0 + 2 * s) : (dWH1 + 2 * (s - 4));
                    uint64_t bl_d = (s < 4) ? (dWL0 + 2 * s) : (dWL1 + 2 * (s - 4));
                    mma_tf32_ts(tmem + TD, tmem + TXH + 8 * s, bh_d, IDESC_A,
                                !(c == 0 && s == 0));
                    mma_tf32_ts(tmem + TD, tmem + TXL + 8 * s, bh_d, IDESC_A, true);
                    mma_tf32_ts(tmem + TD, tmem + TXH + 8 * s, bl_d, IDESC_A, true);
                }
                TC_COMMIT(base + GT_MBAR);
            }
        }
        MBAR_WAIT(base + GT_MBAR, c & 1);
        TC_FENCE_AFTER();
        __syncthreads();
    }

    uint32_t d0[32], d1[32];
    TC_LD_X32(d0, tmem + TD);
    TC_LD_X32(d1, tmem + TD + 32);
    TC_WAIT_LD();
    TC_FENCE_BEFORE();

    const int bb = m0 >> 11;
    const int sidx = (m0 & 2047) + tid;
    const float* bs = (const float*)(sm + GT_BIAS);

    if (which != 2) {
        float* outbuf = (which == 0) ? g_q : g_k;
        float* rowp = outbuf + ((size_t)(bb * HEADS + hh) * SEQ + sidx) * DH;
        const float* ep = (which == 0)
            ? etype + (size_t)(m0 + tid) * EDIM + e0 : nullptr;
        #pragma unroll
        for (int n4 = 0; n4 < 16; n4++) {
            const uint32_t* dr = (n4 < 8) ? d0 : d1;
            int j = (n4 & 7) * 4;
            float4 v;
            v.x = __uint_as_float(dr[j+0]) + bs[n4*4+0];
            v.y = __uint_as_float(dr[j+1]) + bs[n4*4+1];
            v.z = __uint_as_float(dr[j+2]) + bs[n4*4+2];
            v.w = __uint_as_float(dr[j+3]) + bs[n4*4+3];
            if (which == 0) {
                float4 e4 = *(const float4*)&ep[n4*4];
                v.x += e4.x; v.y += e4.y; v.z += e4.z; v.w += e4.w;
            }
            *(float4*)&rowp[n4*4] = v;
        }
    } else {
        float* vb = g_v + ((size_t)(bb * HEADS + hh) * DH) * SEQ + sidx;
        #pragma unroll
        for (int n = 0; n < 32; n++)
            vb[(size_t)n * SEQ] = __uint_as_float(d0[n]) + bs[n];
        #pragma unroll
        for (int n = 0; n < 32; n++)
            vb[(size_t)(n + 32) * SEQ] = __uint_as_float(d1[n]) + bs[n + 32];
    }
    __syncthreads();
    if (wid == 0) TC_DEALLOC(tmem, 256);

#else  // ------------- fp32 fallback GEMM (non-'a' compile pass) -------------
    const int bb = m0 >> 11;
    const int sidx = (m0 & 2047) + tid;
    float acc[64];
    #pragma unroll
    for (int n = 0; n < 64; n++) acc[n] = 0.f;
    for (int k = 0; k < FDIM; k++) {
        float a = x[(size_t)(m0 + tid) * FDIM + k];
        #pragma unroll 16
        for (int n = 0; n < 64; n++)
            acc[n] += a * g_wt[(size_t)(n0g + n) * FDIM + k];
    }
    if (which != 2) {
        float* outbuf = (which == 0) ? g_q : g_k;
        float* rowp = outbuf + ((size_t)(bb * HEADS + hh) * SEQ + sidx) * DH;
        for (int n = 0; n < 64; n++) {
            float v = acc[n] + bias[e0 + n];
            if (which == 0) v += etype[(size_t)(m0 + tid) * EDIM + e0 + n];
            rowp[n] = v;
        }
    } else {
        float* vb = g_v + ((size_t)(bb * HEADS + hh) * DH) * SEQ + sidx;
        for (int n = 0; n < 64; n++)
            vb[(size_t)n * SEQ] = acc[n] + bias[e0 + n];
    }
#endif
}

// ===========================================================================
// tcgen05 bf16x3 attention — 128-key tiles, 16 iterations, single-buffered
// staging (double-buffering measured neutral), V hi/lo (fixes round-10's
// 1.35e-3 V-truncation error).
// TMEM: Qhi[0..31], Qlo[32..63] (bf16x2), S/P [64..191] (S fp32; P bf16x2
// in place: per 64-key group g, Ph = cols 64+64g..+31, Pl = +32..+63),
// O [192..255]. SMEM buffer: K hi/lo 16+16KB, Vt hi/lo 16+16KB = 64KB.
// ===========================================================================
#define TQH 0
#define TQL 32
#define TSP 64
#define TTO 192
#define SM_TMEMPTR 0
#define SM_MBAR_S  16
#define SM_MBAR_PV 24
#define SM_KEEP    64                  // 128 floats
#define SM_LSUM    576                 // 256 floats
#define SM_BUF     2048
#define OFF_KH     0                   // K hi  [128k x 64d bf16] 16KB
#define OFF_KL     16384               // K lo
#define OFF_VH     32768               // Vt hi: 2 chunks [64d x 64k bf16] 8KB
#define OFF_VL     49152               // Vt lo
#define SM_TOTAL   (SM_BUF + 65536)    // 67584

__global__ __launch_bounds__(256, 2)
void attn_tc(const int* __restrict__ mask, float* __restrict__ out)
{
    extern __shared__ char smem[];
    const int tid = threadIdx.x;
    const int bh = blockIdx.y, b = bh >> 3, h = bh & 7;
    const int q0 = blockIdx.x * 128;

#if TC_ENABLED
    const uint32_t smem_base = smem_u32(smem);
    const int wid = tid >> 5;
    const uint32_t warpoff = (uint32_t)(wid & 3) << 21;
    const int grp = wid >> 2;                  // 0: keys 0-63, 1: keys 64-127

    if (wid == 0) { TC_ALLOC(smem_base + SM_TMEMPTR, 256); TC_RELINQ(); }
    __syncthreads();
    uint32_t tmem;
    asm volatile("ld.shared.b32 %0, [%1];" : "=r"(tmem) : "r"(smem_base + SM_TMEMPTR));

    if (tid == 0) {
        MBAR_INIT(smem_base + SM_MBAR_S, 1);
        MBAR_INIT(smem_base + SM_MBAR_PV, 1);
    }

    // Q -> TMEM bf16x2 hi/lo (warps 0-3; thread = query row; scaled 1/8)
    if (tid < 128) {
        const float4* qp = (const float4*)(g_q + ((size_t)bh * SEQ + q0 + tid) * DH);
        uint32_t qh[32], ql[32];
        #pragma unroll
        for (int i = 0; i < 16; i++) {
            float4 v = qp[i];
            bf16_split2(v.x * 0.125f, v.y * 0.125f, qh[i*2+0], ql[i*2+0]);
            bf16_split2(v.z * 0.125f, v.w * 0.125f, qh[i*2+1], ql[i*2+1]);
        }
        TC_ST_X32(tmem + TQH + warpoff, qh);
        TC_ST_X32(tmem + TQL + warpoff, ql);
        TC_WAIT_ST();
        TC_FENCE_BEFORE();
    }
    __syncthreads();

    const uint64_t dKH = MKDESC(smem_base + SM_BUF + OFF_KH);
    const uint64_t dKL = MKDESC(smem_base + SM_BUF + OFF_KL);
    float* keepf = (float*)(smem + SM_KEEP);
    float lsum = 0.f;

    for (int t = 0; t < 16; t++) {
        const int kt0 = t * 128;
        // PV(t-1) completion protects the SMEM buffer and TSP (in-place S/P).
        if (t > 0) MBAR_WAIT(smem_base + SM_MBAR_PV, (t - 1) & 1);

        // --- Stage K tile [128k x 64d] bf16 hi/lo ---
        {
            const float4* kg = (const float4*)(g_k + ((size_t)bh * SEQ + kt0) * DH);
            #pragma unroll
            for (int i = 0; i < 4; i++) {
                int idx = tid + i * 256;
                int r = idx >> 3, seg = idx & 7;
                float4 v0 = kg[r * 16 + seg * 2];
                float4 v1 = kg[r * 16 + seg * 2 + 1];
                uint4 hi, lo;
                bf16_split2(v0.x, v0.y, hi.x, lo.x);
                bf16_split2(v0.z, v0.w, hi.y, lo.y);
                bf16_split2(v1.x, v1.y, hi.z, lo.z);
                bf16_split2(v1.z, v1.w, hi.w, lo.w);
                uint32_t o = SWZ128((uint32_t)(r * 128 + seg * 16));
                *(uint4*)(smem + SM_BUF + OFF_KH + o) = hi;
                *(uint4*)(smem + SM_BUF + OFF_KL + o) = lo;
            }
            // --- Stage Vt tile [64d x 128k] bf16 hi/lo, 2 chunks of 64 keys ---
            #pragma unroll
            for (int i = 0; i < 4; i++) {
                int idx = tid + i * 256;
                int d = idx >> 4, rest = idx & 15;
                int c = rest >> 3, seg = rest & 7;
                const float* vp = g_v + ((size_t)bh * DH + d) * SEQ + kt0 + c * 64 + seg * 8;
                float4 v0 = *(const float4*)vp;
                float4 v1 = *(const float4*)(vp + 4);
                uint4 hv, lv;
                bf16_split2(v0.x, v0.y, hv.x, lv.x);
                bf16_split2(v0.z, v0.w, hv.y, lv.y);
                bf16_split2(v1.x, v1.y, hv.z, lv.z);
                bf16_split2(v1.z, v1.w, hv.w, lv.w);
                uint32_t o = SWZ128((uint32_t)(d * 128 + seg * 16));
                *(uint4*)(smem + SM_BUF + OFF_VH + c * 8192 + o) = hv;
                *(uint4*)(smem + SM_BUF + OFF_VL + c * 8192 + o) = lv;
            }
            if (tid < 128)
                keepf[tid] = (mask[b * SEQ + kt0 + tid] == 1) ? 1.f : 0.f;
        }
        __syncthreads();

        // --- S(t) = Qh@Kh + Ql@Kh + Qh@Kl  (4 K-steps of K=16 bf16) ---
        if (wid == 0) {
            TC_FENCE_AFTER();
            if (elect_one()) {
                #pragma unroll
                for (int s = 0; s < 4; s++) {
                    mma_f16_ts(tmem + TSP, tmem + TQH + 8 * s, dKH + 2 * s,
                               IDESC_BS, s > 0);
                    mma_f16_ts(tmem + TSP, tmem + TQL + 8 * s, dKH + 2 * s,
                               IDESC_BS, true);
                    mma_f16_ts(tmem + TSP, tmem + TQH + 8 * s, dKL + 2 * s,
                               IDESC_BS, true);
                }
                TC_COMMIT(smem_base + SM_MBAR_S);
            }
        }
        MBAR_WAIT(smem_base + SM_MBAR_S, t & 1);
        TC_FENCE_AFTER();

        // --- exp + pack P bf16x2 hi/lo in place. Warp covers keys grp*64..+63 ---
        {
            const uint32_t sbase = tmem + TSP + grp * 64;
            uint32_t sr0[32], sr1[32];
            TC_LD_X32(sr0, sbase);
            TC_LD_X32(sr1, sbase + 32);
            TC_WAIT_LD();
            const int kb = grp * 64;
            #pragma unroll
            for (int g = 0; g < 2; g++) {
                const uint32_t* sr = g ? sr1 : sr0;
                uint32_t ph[16], pl[16];
                #pragma unroll
                for (int i = 0; i < 16; i++) {
                    float s0 = __uint_as_float(sr[2*i]);
                    float s1 = __uint_as_float(sr[2*i+1]);
                    int k0i = kb + g * 32 + 2 * i;
                    float p0 = keepf[k0i]     * __expf(s0);
                    float p1 = keepf[k0i + 1] * __expf(s1);
                    lsum += p0 + p1;
                    bf16_split2(p0, p1, ph[i], pl[i]);
                }
                TC_ST_X16(sbase + g * 16 + warpoff, ph);
                TC_ST_X16(sbase + 32 + g * 16 + warpoff, pl);
            }
        }
        TC_WAIT_ST();
        TC_FENCE_BEFORE();
        __syncthreads();

        // --- PV(t): Ph@Vh + Pl@Vh + Ph@Vl  (8 K-steps of 16 keys) ---
        if (wid == 0) {
            TC_FENCE_AFTER();
            if (elect_one()) {
                #pragma unroll
                for (int s = 0; s < 8; s++) {
                    uint32_t a_hi = tmem + TSP + ((s < 4) ? (8 * s) : (64 + 8 * (s - 4)));
                    uint32_t coff = (s >> 2) * 8192 + 0;
                    uint64_t bdh = MKDESC(smem_base + SM_BUF + OFF_VH + (s >> 2) * 8192) + 2 * (s & 3);
                    uint64_t bdl = MKDESC(smem_base + SM_BUF + OFF_VL + (s >> 2) * 8192) + 2 * (s & 3);
                    (void)coff;
                    mma_f16_ts(tmem + TTO, a_hi, bdh, IDESC_BPV, !(t == 0 && s == 0));
                    mma_f16_ts(tmem + TTO, a_hi + 32, bdh, IDESC_BPV, true);
                    mma_f16_ts(tmem + TTO, a_hi, bdl, IDESC_BPV, true);
                }
                TC_COMMIT(smem_base + SM_MBAR_PV);
            }
        }
    }

    MBAR_WAIT(smem_base + SM_MBAR_PV, 1);    // 16th commit (t=15) -> parity 1
    TC_FENCE_AFTER();

    float* lsums = (float*)(smem + SM_LSUM);
    lsums[tid] = lsum;
    __syncthreads();

    if (tid < 128) {
        const float ltot = lsums[tid] + lsums[tid + 128];
        uint32_t o0[32], o1[32];
        TC_LD_X32(o0, tmem + TTO);
        TC_LD_X32(o1, tmem + TTO + 32);
        TC_WAIT_LD();
        TC_FENCE_BEFORE();

        const int sq = q0 + tid;
        const float inv = (mask[b * SEQ + sq] == 1) ? (1.f / ltot) : 0.f;
        float* op = out + ((size_t)b * SEQ + sq) * EDIM + h * DH;
        #pragma unroll
        for (int i = 0; i < 8; i++) {
            float4 v;
            v.x = __uint_as_float(o0[i*4+0]) * inv;
            v.y = __uint_as_float(o0[i*4+1]) * inv;
            v.z = __uint_as_float(o0[i*4+2]) * inv;
            v.w = __uint_as_float(o0[i*4+3]) * inv;
            *(float4*)&op[i * 4] = v;
        }
        #pragma unroll
        for (int i = 0; i < 8; i++) {
            float4 v;
            v.x = __uint_as_float(o1[i*4+0]) * inv;
            v.y = __uint_as_float(o1[i*4+1]) * inv;
            v.z = __uint_as_float(o1[i*4+2]) * inv;
            v.w = __uint_as_float(o1[i*4+3]) * inv;
            *(float4*)&op[32 + i * 4] = v;
        }
    }

    __syncthreads();
    if (wid == 0) TC_DEALLOC(tmem, 256);

#else  // ---------------- fp32 fallback (non-'a' compile pass) ----------------
    float* ks    = (float*)smem;
    float* vs    = (float*)(smem + 16384);
    float* keepf = (float*)(smem + 32768);

    const int sq = q0 + (tid & 127);
    const float* qptr = g_q + ((size_t)bh * SEQ + sq) * DH;
    float q[DH];
    #pragma unroll
    for (int d = 0; d < DH; d++) q[d] = qptr[d] * 0.125f;
    float lsum = 0.f;
    float acc[DH];
    #pragma unroll
    for (int d = 0; d < DH; d++) acc[d] = 0.f;

    for (int kt0 = 0; kt0 < SEQ; kt0 += 64) {
        __syncthreads();
        const float4* kg = (const float4*)(g_k + ((size_t)bh * SEQ + kt0) * DH);
        #pragma unroll
        for (int i = 0; i < 4; i++) {
            int idx = tid + i * 256;
            ((float4*)ks)[idx] = kg[idx];
            int d = idx >> 4, f = idx & 15;
            float4 v = *(const float4*)(g_v + ((size_t)bh * DH + d) * SEQ + kt0 + f * 4);
            vs[(f*4+0)*64 + d] = v.x; vs[(f*4+1)*64 + d] = v.y;
            vs[(f*4+2)*64 + d] = v.z; vs[(f*4+3)*64 + d] = v.w;
        }
        if (tid < 64)
            keepf[tid] = (mask[b * SEQ + kt0 + tid] == 1) ? 1.f : 0.f;
        __syncthreads();

        if (tid < 128) {
            for (int j = 0; j < 64; j++) {
                const float* kr = ks + j * 64;
                float s = 0.f;
                #pragma unroll
                for (int d = 0; d < DH; d++) s += q[d] * kr[d];
                float p = keepf[j] * __expf(s);
                lsum += p;
                const float* vr = vs + j * 64;
                #pragma unroll
                for (int d = 0; d < DH; d++) acc[d] += p * vr[d];
            }
        }
    }
    if (tid < 128) {
        const float inv = (mask[b * SEQ + sq] == 1) ? (1.f / lsum) : 0.f;
        float* op = out + ((size_t)b * SEQ + sq) * EDIM + h * DH;
        #pragma unroll
        for (int d = 0; d < DH; d++) op[d] = acc[d] * inv;
    }
#endif
}

// ===========================================================================
extern "C" void kernel_launch(void* const* d_in, const int* in_sizes, int n_in,
                              void* d_out, int out_size)
{
    const float* x     = (const float*)d_in[0];
    const float* etype = (const float*)d_in[1];
    const int*   mask  = (const int*)  d_in[2];
    const float* Wq    = (const float*)d_in[3];
    const float* bq    = (const float*)d_in[4];
    const float* Wk    = (const float*)d_in[5];
    const float* bk    = (const float*)d_in[6];
    const float* Wv    = (const float*)d_in[7];
    const float* bv    = (const float*)d_in[8];
    float* out = (float*)d_out;

    static int smem_set = 0;
    if (!smem_set) {
        cudaFuncSetAttribute(tc_gemm, cudaFuncAttributeMaxDynamicSharedMemorySize, GT_TOTAL);
        cudaFuncSetAttribute(attn_tc, cudaFuncAttributeMaxDynamicSharedMemorySize, SM_TOTAL);
        smem_set = 1;
    }

    cvt_wt<<<dim3(16, 16, 3), 256>>>(Wq, Wk, Wv);

    dim3 ggrid(MROWS / 128, (3 * EDIM) / 64);    // 64 x 24
    tc_gemm<<<ggrid, 128, GT_TOTAL>>>(x, etype, bq, bk, bv);

    dim3 agrid(SEQ / 128, BATCH * HEADS);        // 16 x 32
    attn_tc<<<agrid, 256, SM_TOTAL>>>(mask, out);
}

// round 14
// speedup vs baseline: 1.3535x; 1.3535x over previous
#include <cuda_runtime.h>
#include <cuda_bf16.h>
#include <cstdint>

// Problem constants
#define BATCH 4
#define SEQ   2048
#define FDIM  512
#define EDIM  512
#define HEADS 8
#define DH    64
#define MROWS (BATCH*SEQ)      // 8192

// tcgen05 only exists in arch-accelerated ('a') compilation passes.
#if defined(__CUDA_ARCH_FEAT_SM103_ALL) || defined(__CUDA_ARCH_FEAT_SM100_ALL) || \
    defined(__CUDA_ARCH_SPECIFIC__) || defined(__CUDA_ARCH_FAMILY_SPECIFIC__)
#define TC_ENABLED 1
#else
#define TC_ENABLED 0
#endif

// Scratch: Q/K in [B,H,S,DH]; V stored TRANSPOSED [B,H,DH,S] (all fp32).
__device__ float g_q[(size_t)BATCH*HEADS*SEQ*DH];
__device__ float g_k[(size_t)BATCH*HEADS*SEQ*DH];
__device__ float g_v[(size_t)BATCH*HEADS*DH*SEQ];
// W^T concat [1536 n][512 k] fp32 (Wq^T | Wk^T | Wv^T), written by cvt_wt.
__device__ float g_wt[(size_t)3*EDIM*FDIM];

// ===========================================================================
// PTX helpers
// ===========================================================================
__device__ __forceinline__ uint32_t smem_u32(const void* p) {
    uint32_t a;
    asm("{ .reg .u64 t; cvta.to.shared.u64 t, %1; cvt.u32.u64 %0, t; }" : "=r"(a) : "l"(p));
    return a;
}
__device__ __forceinline__ bool elect_one() {
    uint32_t pred;
    asm volatile("{\n\t.reg .pred p;\n\telect.sync _|p, 0xFFFFFFFF;\n\t"
                 "selp.b32 %0, 1, 0, p;\n\t}" : "=r"(pred));
    return pred != 0;
}
__device__ __forceinline__ float rna_tf32(float x) {
    uint32_t u;
    asm("cvt.rna.tf32.f32 %0, %1;" : "=r"(u) : "f"(x));
    return __uint_as_float(u);
}
__device__ __forceinline__ uint32_t rna_tf32_bits(float x) {
    uint32_t u;
    asm("cvt.rna.tf32.f32 %0, %1;" : "=r"(u) : "f"(x));
    return u;
}
// bf16 hi/lo split of a pair (a=low half, b=high half)
__device__ __forceinline__ void bf16_split2(float a, float b, uint32_t& h, uint32_t& l) {
    __nv_bfloat16 ha = __float2bfloat16(a), hb = __float2bfloat16(b);
    float ra = a - __bfloat162float(ha);
    float rb = b - __bfloat162float(hb);
    __nv_bfloat16 la = __float2bfloat16(ra), lb = __float2bfloat16(rb);
    h = ((uint32_t)__bfloat16_as_ushort(hb) << 16) | __bfloat16_as_ushort(ha);
    l = ((uint32_t)__bfloat16_as_ushort(lb) << 16) | __bfloat16_as_ushort(la);
}

#define TC_ALLOC(smem_addr, n) \
    asm volatile("tcgen05.alloc.cta_group::1.sync.aligned.shared::cta.b32 [%0], %1;" \
                 :: "r"(smem_addr), "r"((uint32_t)(n)) : "memory")
#define TC_RELINQ() \
    asm volatile("tcgen05.relinquish_alloc_permit.cta_group::1.sync.aligned;")
#define TC_DEALLOC(tmem_addr, n) \
    asm volatile("tcgen05.dealloc.cta_group::1.sync.aligned.b32 %0, %1;" \
                 :: "r"(tmem_addr), "r"((uint32_t)(n)))
#define TC_WAIT_ST() asm volatile("tcgen05.wait::st.sync.aligned;" ::: "memory")
#define TC_WAIT_LD() asm volatile("tcgen05.wait::ld.sync.aligned;" ::: "memory")
#define TC_FENCE_BEFORE() asm volatile("tcgen05.fence::before_thread_sync;" ::: "memory")
#define TC_FENCE_AFTER()  asm volatile("tcgen05.fence::after_thread_sync;" ::: "memory")
#define TC_COMMIT(mbar) \
    asm volatile("tcgen05.commit.cta_group::1.mbarrier::arrive::one.shared::cluster.b64 [%0];" \
                 :: "r"((uint32_t)(mbar)) : "memory")

#define TC_ST_X32(tmem_addr, r) \
    asm volatile("tcgen05.st.sync.aligned.32x32b.x32.b32 [%0], " \
        "{%1, %2, %3, %4, %5, %6, %7, %8, %9, %10, %11, %12, %13, %14, %15, %16, " \
        " %17, %18, %19, %20, %21, %22, %23, %24, %25, %26, %27, %28, %29, %30, %31, %32};" \
        :: "r"(tmem_addr), \
           "r"((r)[0]),"r"((r)[1]),"r"((r)[2]),"r"((r)[3]),"r"((r)[4]),"r"((r)[5]),"r"((r)[6]),"r"((r)[7]), \
           "r"((r)[8]),"r"((r)[9]),"r"((r)[10]),"r"((r)[11]),"r"((r)[12]),"r"((r)[13]),"r"((r)[14]),"r"((r)[15]), \
           "r"((r)[16]),"r"((r)[17]),"r"((r)[18]),"r"((r)[19]),"r"((r)[20]),"r"((r)[21]),"r"((r)[22]),"r"((r)[23]), \
           "r"((r)[24]),"r"((r)[25]),"r"((r)[26]),"r"((r)[27]),"r"((r)[28]),"r"((r)[29]),"r"((r)[30]),"r"((r)[31]) \
        : "memory")

#define TC_LD_X32(r, tmem_addr) \
    asm volatile("tcgen05.ld.sync.aligned.32x32b.x32.b32 " \
        "{%0, %1, %2, %3, %4, %5, %6, %7, %8, %9, %10, %11, %12, %13, %14, %15, " \
        " %16, %17, %18, %19, %20, %21, %22, %23, %24, %25, %26, %27, %28, %29, %30, %31}, [%32];" \
        : "=r"((r)[0]),"=r"((r)[1]),"=r"((r)[2]),"=r"((r)[3]),"=r"((r)[4]),"=r"((r)[5]),"=r"((r)[6]),"=r"((r)[7]), \
          "=r"((r)[8]),"=r"((r)[9]),"=r"((r)[10]),"=r"((r)[11]),"=r"((r)[12]),"=r"((r)[13]),"=r"((r)[14]),"=r"((r)[15]), \
          "=r"((r)[16]),"=r"((r)[17]),"=r"((r)[18]),"=r"((r)[19]),"=r"((r)[20]),"=r"((r)[21]),"=r"((r)[22]),"=r"((r)[23]), \
          "=r"((r)[24]),"=r"((r)[25]),"=r"((r)[26]),"=r"((r)[27]),"=r"((r)[28]),"=r"((r)[29]),"=r"((r)[30]),"=r"((r)[31]) \
        : "r"(tmem_addr))

#define MBAR_INIT(mbar, cnt) \
    asm volatile("mbarrier.init.shared.b64 [%0], %1;" :: "r"((uint32_t)(mbar)), "r"((uint32_t)(cnt)) : "memory")

#define MBAR_WAIT(mbar, parity) do { \
    uint32_t _m = (uint32_t)(mbar); uint32_t _p = (uint32_t)(parity); uint32_t _done; \
    asm volatile("{\n\t.reg .pred p;\n\t" \
        "mbarrier.try_wait.parity.acquire.cta.shared::cta.b64 p, [%1], %2;\n\t" \
        "selp.b32 %0, 1, 0, p;\n\t}" : "=r"(_done) : "r"(_m), "r"(_p) : "memory"); \
    if (!_done) { \
        asm volatile("{\n\t.reg .pred P1;\n\t" \
            "WAIT_LOOP_%=:\n\t" \
            "mbarrier.try_wait.parity.acquire.cta.shared::cta.b64 P1, [%0], %1, 0x989680;\n\t" \
            "@P1 bra.uni WAIT_DONE_%=;\n\t" \
            "bra.uni WAIT_LOOP_%=;\n\t" \
            "WAIT_DONE_%=:\n\t}" :: "r"(_m), "r"(_p) : "memory"); \
    } \
} while (0)

// SW128 SMEM descriptor (layout=2, version=1, SBO=64, LBO=1)
#define SMEM_DESC_BASE_SW128 \
    ((uint64_t(2) << 61) | (uint64_t(1) << 46) | (uint64_t(64) << 32) | (uint64_t(1) << 16))
#define MKDESC(addr) (SMEM_DESC_BASE_SW128 | ((uint64_t)((addr) >> 4) & 0x3FFF))
#define SWZ128(o) ((o) ^ (((o) >> 3) & 0x70))

#if TC_ENABLED
__device__ __forceinline__ void mma_tf32_ts(uint32_t d, uint32_t a, uint64_t bdesc,
                                            uint32_t idesc, bool acc) {
    uint32_t e = acc ? 1u : 0u;
    asm volatile("{\n\t.reg .pred p;\n\tsetp.ne.u32 p, %4, 0;\n\t"
        "tcgen05.mma.cta_group::1.kind::tf32 [%0], [%1], %2, %3, p;\n\t}"
        :: "r"(d), "r"(a), "l"(bdesc), "r"(idesc), "r"(e) : "memory");
}
__device__ __forceinline__ void mma_f16_ts(uint32_t d, uint32_t a, uint64_t bdesc,
                                           uint32_t idesc, bool acc) {
    uint32_t e = acc ? 1u : 0u;
    asm volatile("{\n\t.reg .pred p;\n\tsetp.ne.u32 p, %5, 0;\n\t"
        "tcgen05.mma.cta_group::1.kind::f16 [%0], [%1], %2, %3, {%4, %4, %4, %4}, p;\n\t}"
        :: "r"(d), "r"(a), "l"(bdesc), "r"(idesc), "r"(0u), "r"(e) : "memory");
}
#endif

// tf32 idesc (attention, round-9 proven): M=128, N=64
#define IDESC_A ((1u<<4)|(2u<<7)|(2u<<10)|((64u/8)<<17)|((128u/16)<<24))
// bf16 idesc (GEMM): M=128, N=64 — same constant proven as round-11 PV idesc
#define IDESC_G ((1u<<4)|(1u<<7)|(1u<<10)|((64u/8)<<17)|((128u/16)<<24))

// ===========================================================================
// cvt_wt (proven, unchanged)
// ===========================================================================
__global__ __launch_bounds__(256)
void cvt_wt(const float* __restrict__ Wq, const float* __restrict__ Wk,
            const float* __restrict__ Wv)
{
    __shared__ float t[32][33];
    const int z = blockIdx.z;
    const float* W = (z == 0) ? Wq : (z == 1) ? Wk : Wv;
    const int k0 = blockIdx.x * 32;
    const int n0 = blockIdx.y * 32;
    const int tx = threadIdx.x & 31;
    const int ty = threadIdx.x >> 5;
    #pragma unroll
    for (int i = 0; i < 4; i++)
        t[ty + 8*i][tx] = W[(size_t)(k0 + ty + 8*i) * EDIM + n0 + tx];
    __syncthreads();
    #pragma unroll
    for (int i = 0; i < 4; i++)
        g_wt[(size_t)(z * EDIM + n0 + ty + 8*i) * FDIM + k0 + tx] = t[tx][ty + 8*i];
}

// ===========================================================================
// tcgen05 bf16x3 projection GEMM — round-8 skeleton + epilogue (PROVEN),
// bf16 operands via proven attention patterns (Q-load, K-tile, PV idesc).
// TMEM: Xh[0..31], Xl[32..63] (bf16x2), D[64..127] fp32. Alloc 128 -> occ 4.
// ===========================================================================
#define TXH 0
#define TXL 32
#define TD  64
#define GT_TMEMPTR 0
#define GT_MBAR    16
#define GT_BIAS    64                  // 64 floats
#define GT_WH      1024                // W^T hi [64n x 64k bf16] SW128, 8KB
#define GT_WL      (GT_WH + 8192)
#define GT_TOTAL   (GT_WL + 8192)      // 17408

__global__ __launch_bounds__(128)
void tc_gemm(const float* __restrict__ x,
             const float* __restrict__ etype,
             const float* __restrict__ bq, const float* __restrict__ bk,
             const float* __restrict__ bv)
{
    extern __shared__ char sm[];
    const int tid = threadIdx.x;
    const int m0 = blockIdx.x * 128;
    const int n0g = blockIdx.y * 64;
    const int which = n0g >> 9;
    const int e0 = n0g & 511;
    const int hh = e0 >> 6;
    const float* bias = (which == 0) ? bq : (which == 1) ? bk : bv;

#if TC_ENABLED
    const uint32_t base = smem_u32(sm);
    const int wid = tid >> 5;
    const uint32_t warpoff = (uint32_t)wid << 21;

    if (wid == 0) { TC_ALLOC(base + GT_TMEMPTR, 128); TC_RELINQ(); }
    __syncthreads();
    uint32_t tmem;
    asm volatile("ld.shared.b32 %0, [%1];" : "=r"(tmem) : "r"(base + GT_TMEMPTR));
    if (tid == 0) MBAR_INIT(base + GT_MBAR, 1);
    if (tid < 64) ((float*)(sm + GT_BIAS))[tid] = bias[e0 + tid];
    __syncthreads();

    const uint64_t dWH = MKDESC(base + GT_WH);
    const uint64_t dWL = MKDESC(base + GT_WL);

    for (int c = 0; c < 8; c++) {
        const int k0 = c * 64;
        // --- Stage W^T tile [64n x 64k] bf16 hi/lo (attention K-tile pattern) ---
        #pragma unroll
        for (int i = 0; i < 4; i++) {
            int idx = tid + i * 128;            // 512 units of 16B
            int r = idx >> 3, seg = idx & 7;
            const float* wp = &g_wt[(size_t)(n0g + r) * FDIM + k0 + seg * 8];
            float4 v0 = *(const float4*)wp;
            float4 v1 = *(const float4*)(wp + 4);
            uint4 hi, lo;
            bf16_split2(v0.x, v0.y, hi.x, lo.x);
            bf16_split2(v0.z, v0.w, hi.y, lo.y);
            bf16_split2(v1.x, v1.y, hi.z, lo.z);
            bf16_split2(v1.z, v1.w, hi.w, lo.w);
            uint32_t o = SWZ128((uint32_t)(r * 128 + seg * 16));
            *(uint4*)(sm + GT_WH + o) = hi;
            *(uint4*)(sm + GT_WL + o) = lo;
        }
        // --- x chunk -> TMEM bf16x2 hi/lo (attention Q-load pattern) ---
        {
            const float4* xp = (const float4*)(x + (size_t)(m0 + tid) * FDIM + k0);
            uint32_t rh[32], rl[32];
            #pragma unroll
            for (int i = 0; i < 16; i++) {
                float4 v = xp[i];
                bf16_split2(v.x, v.y, rh[i*2+0], rl[i*2+0]);
                bf16_split2(v.z, v.w, rh[i*2+1], rl[i*2+1]);
            }
            TC_ST_X32(tmem + TXH + warpoff, rh);
            TC_ST_X32(tmem + TXL + warpoff, rl);
            TC_WAIT_ST();
        }
        TC_FENCE_BEFORE();
        __syncthreads();

        // --- D += Xh@Wh + Xl@Wh + Xh@Wl  (4 K-steps of K=16 bf16) ---
        if (wid == 0) {
            TC_FENCE_AFTER();
            if (elect_one()) {
                #pragma unroll
                for (int s = 0; s < 4; s++) {
                    mma_f16_ts(tmem + TD, tmem + TXH + 8 * s, dWH + 2 * s, IDESC_G,
                               !(c == 0 && s == 0));
                    mma_f16_ts(tmem + TD, tmem + TXL + 8 * s, dWH + 2 * s, IDESC_G, true);
                    mma_f16_ts(tmem + TD, tmem + TXH + 8 * s, dWL + 2 * s, IDESC_G, true);
                }
                TC_COMMIT(base + GT_MBAR);
            }
        }
        // SERIALIZE (round-8 proven): wait before restaging.
        MBAR_WAIT(base + GT_MBAR, c & 1);
        TC_FENCE_AFTER();
        __syncthreads();
    }

    // --- Epilogue: round-8 PROVEN, fp32 outputs. Thread tid = row m0+tid ---
    uint32_t d0[32], d1[32];
    TC_LD_X32(d0, tmem + TD);
    TC_LD_X32(d1, tmem + TD + 32);
    TC_WAIT_LD();
    TC_FENCE_BEFORE();

    const int bb = m0 >> 11;
    const int sidx = (m0 & 2047) + tid;
    const float* bs = (const float*)(sm + GT_BIAS);

    if (which != 2) {
        float* outbuf = (which == 0) ? g_q : g_k;
        float* rowp = outbuf + ((size_t)(bb * HEADS + hh) * SEQ + sidx) * DH;
        const float* ep = (which == 0)
            ? etype + (size_t)(m0 + tid) * EDIM + e0 : nullptr;
        #pragma unroll
        for (int n4 = 0; n4 < 16; n4++) {
            const uint32_t* dr = (n4 < 8) ? d0 : d1;
            int j = (n4 & 7) * 4;
            float4 v;
            v.x = __uint_as_float(dr[j+0]) + bs[n4*4+0];
            v.y = __uint_as_float(dr[j+1]) + bs[n4*4+1];
            v.z = __uint_as_float(dr[j+2]) + bs[n4*4+2];
            v.w = __uint_as_float(dr[j+3]) + bs[n4*4+3];
            if (which == 0) {
                float4 e4 = *(const float4*)&ep[n4*4];
                v.x += e4.x; v.y += e4.y; v.z += e4.z; v.w += e4.w;
            }
            *(float4*)&rowp[n4*4] = v;
        }
    } else {
        float* vb = g_v + ((size_t)(bb * HEADS + hh) * DH) * SEQ + sidx;
        #pragma unroll
        for (int n = 0; n < 32; n++)
            vb[(size_t)n * SEQ] = __uint_as_float(d0[n]) + bs[n];
        #pragma unroll
        for (int n = 0; n < 32; n++)
            vb[(size_t)(n + 32) * SEQ] = __uint_as_float(d1[n]) + bs[n + 32];
    }
    __syncthreads();
    if (wid == 0) TC_DEALLOC(tmem, 128);

#else  // ------------- fp32 fallback GEMM (non-'a' compile pass) -------------
    const int bb = m0 >> 11;
    const int sidx = (m0 & 2047) + tid;
    float acc[64];
    #pragma unroll
    for (int n = 0; n < 64; n++) acc[n] = 0.f;
    for (int k = 0; k < FDIM; k++) {
        float a = x[(size_t)(m0 + tid) * FDIM + k];
        #pragma unroll 16
        for (int n = 0; n < 64; n++)
            acc[n] += a * g_wt[(size_t)(n0g + n) * FDIM + k];
    }
    if (which != 2) {
        float* outbuf = (which == 0) ? g_q : g_k;
        float* rowp = outbuf + ((size_t)(bb * HEADS + hh) * SEQ + sidx) * DH;
        for (int n = 0; n < 64; n++) {
            float v = acc[n] + bias[e0 + n];
            if (which == 0) v += etype[(size_t)(m0 + tid) * EDIM + e0 + n];
            rowp[n] = v;
        }
    } else {
        float* vb = g_v + ((size_t)(bb * HEADS + hh) * DH) * SEQ + sidx;
        for (int n = 0; n < 64; n++)
            vb[(size_t)n * SEQ] = acc[n] + bias[e0 + n];
    }
#endif
}

// ===========================================================================
// tcgen05 tf32x3 attention — ROUND-9 PROVEN, byte-identical (326.8us config).
// Double-buffered staging + 256 threads. TMEM: Qhi[0..63], Qlo[64..127],
// S/P in place [128..191], O [192..255].
// ===========================================================================
#define TQH 0
#define TQL 64
#define TSP 128
#define TTO 192
#define SM_TMEMPTR 0
#define SM_MBAR_S  16
#define SM_MBAR_PV 24
#define SM_KEEP0   64
#define SM_KEEP1   320
#define SM_LSUM    576
#define SM_BUF0    2048
#define BUFSZ      49152
#define OFF_KH0    0
#define OFF_KH1    8192
#define OFF_KL0    16384
#define OFF_KL1    24576
#define OFF_VT     32768
#define SM_TOTAL   (SM_BUF0 + 2*BUFSZ) // 100352

__global__ __launch_bounds__(256, 2)
void attn_tc(const int* __restrict__ mask, float* __restrict__ out)
{
    extern __shared__ char smem[];
    const int tid = threadIdx.x;
    const int bh = blockIdx.y, b = bh >> 3, h = bh & 7;
    const int q0 = blockIdx.x * 128;

#if TC_ENABLED
    const uint32_t smem_base = smem_u32(smem);
    const int wid = tid >> 5;
    const uint32_t warpoff = (uint32_t)(wid & 3) << 21;

    if (wid == 0) { TC_ALLOC(smem_base + SM_TMEMPTR, 256); TC_RELINQ(); }
    __syncthreads();
    uint32_t tmem;
    asm volatile("ld.shared.b32 %0, [%1];" : "=r"(tmem) : "r"(smem_base + SM_TMEMPTR));

    if (tid == 0) {
        MBAR_INIT(smem_base + SM_MBAR_S, 1);
        MBAR_INIT(smem_base + SM_MBAR_PV, 1);
    }

    // Q -> TMEM hi/lo (warps 0-3; thread tid = query row; 32-col passes)
    if (tid < 128) {
        const float4* qp = (const float4*)(g_q + ((size_t)bh * SEQ + q0 + tid) * DH);
        #pragma unroll
        for (int half = 0; half < 2; half++) {
            uint32_t rh[32], rl[32];
            #pragma unroll
            for (int i = 0; i < 8; i++) {
                float4 v = qp[half * 8 + i];
                float f[4] = { v.x * 0.125f, v.y * 0.125f, v.z * 0.125f, v.w * 0.125f };
                #pragma unroll
                for (int c = 0; c < 4; c++) {
                    float hi = rna_tf32(f[c]);
                    rh[i*4+c] = __float_as_uint(hi);
                    rl[i*4+c] = rna_tf32_bits(f[c] - hi);
                }
            }
            TC_ST_X32(tmem + TQH + half * 32 + warpoff, rh);
            TC_ST_X32(tmem + TQL + half * 32 + warpoff, rl);
        }
        TC_WAIT_ST();
        TC_FENCE_BEFORE();
    }

    // Stage tile 0 into buffer 0 (all 256 threads)
    {
        const uint32_t bufb = SM_BUF0;
        const float4* kg = (const float4*)(g_k + (size_t)bh * SEQ * DH);
        #pragma unroll
        for (int i = 0; i < 4; i++) {
            int idx = tid + i * 256;
            int r = idx >> 4, c4 = idx & 15;
            float4 v = kg[idx];
            float4 hi, lo;
            hi.x = rna_tf32(v.x); lo.x = rna_tf32(v.x - hi.x);
            hi.y = rna_tf32(v.y); lo.y = rna_tf32(v.y - hi.y);
            hi.z = rna_tf32(v.z); lo.z = rna_tf32(v.z - hi.z);
            hi.w = rna_tf32(v.w); lo.w = rna_tf32(v.w - hi.w);
            uint32_t o = SWZ128((uint32_t)(r * 128 + (c4 & 7) * 16));
            uint32_t hsel = (c4 & 8) ? 8192u : 0u;
            *(float4*)(smem + bufb + OFF_KH0 + hsel + o) = hi;
            *(float4*)(smem + bufb + OFF_KL0 + hsel + o) = lo;
        }
        #pragma unroll
        for (int i = 0; i < 4; i++) {
            int idx = tid + i * 256;
            int d = idx >> 4, kc = idx & 15;
            int c = kc >> 3, f = kc & 7;
            float4 v = *(const float4*)(g_v + ((size_t)bh * DH + d) * SEQ + c * 32 + f * 4);
            v.x = rna_tf32(v.x); v.y = rna_tf32(v.y);
            v.z = rna_tf32(v.z); v.w = rna_tf32(v.w);
            *(float4*)(smem + bufb + OFF_VT + c * 8192 + SWZ128((uint32_t)(d * 128 + f * 16))) = v;
        }
        if (tid < 64)
            ((float*)(smem + SM_KEEP0))[tid] = (mask[b * SEQ + tid] == 1) ? 1.f : 0.f;
    }
    __syncthreads();

    uint64_t dKH0[2], dKH1[2], dKL0[2], dKL1[2];
    #pragma unroll
    for (int bf = 0; bf < 2; bf++) {
        uint32_t bb2 = smem_base + SM_BUF0 + bf * BUFSZ;
        dKH0[bf] = MKDESC(bb2 + OFF_KH0);
        dKH1[bf] = MKDESC(bb2 + OFF_KH1);
        dKL0[bf] = MKDESC(bb2 + OFF_KL0);
        dKL1[bf] = MKDESC(bb2 + OFF_KL1);
    }

    float lsum = 0.f;
    const int colbase = (wid >> 2) * 32;

    for (int t = 0; t < 32; t++) {
        const int cur = t & 1;
        if (t > 0) MBAR_WAIT(smem_base + SM_MBAR_PV, (t - 1) & 1);

        if (wid == 0) {
            TC_FENCE_AFTER();
            if (elect_one()) {
                #pragma unroll
                for (int s = 0; s < 8; s++) {
                    uint64_t bh_d = (s < 4) ? (dKH0[cur] + 2 * s) : (dKH1[cur] + 2 * (s - 4));
                    uint64_t bl_d = (s < 4) ? (dKL0[cur] + 2 * s) : (dKL1[cur] + 2 * (s - 4));
                    mma_tf32_ts(tmem + TSP, tmem + TQH + 8 * s, bh_d, IDESC_A, s > 0);
                    mma_tf32_ts(tmem + TSP, tmem + TQL + 8 * s, bh_d, IDESC_A, true);
                    mma_tf32_ts(tmem + TSP, tmem + TQH + 8 * s, bl_d, IDESC_A, true);
                }
                TC_COMMIT(smem_base + SM_MBAR_S);
            }
        }

        if (t < 31) {
            const int kt1 = (t + 1) * 64;
            const uint32_t bufb = SM_BUF0 + (cur ^ 1) * BUFSZ;
            const float4* kg = (const float4*)(g_k + ((size_t)bh * SEQ + kt1) * DH);
            #pragma unroll
            for (int i = 0; i < 4; i++) {
                int idx = tid + i * 256;
                int r = idx >> 4, c4 = idx & 15;
                float4 v = kg[idx];
                float4 hi, lo;
                hi.x = rna_tf32(v.x); lo.x = rna_tf32(v.x - hi.x);
                hi.y = rna_tf32(v.y); lo.y = rna_tf32(v.y - hi.y);
                hi.z = rna_tf32(v.z); lo.z = rna_tf32(v.z - hi.z);
                hi.w = rna_tf32(v.w); lo.w = rna_tf32(v.w - hi.w);
                uint32_t o = SWZ128((uint32_t)(r * 128 + (c4 & 7) * 16));
                uint32_t hsel = (c4 & 8) ? 8192u : 0u;
                *(float4*)(smem + bufb + OFF_KH0 + hsel + o) = hi;
                *(float4*)(smem + bufb + OFF_KL0 + hsel + o) = lo;
            }
            #pragma unroll
            for (int i = 0; i < 4; i++) {
                int idx = tid + i * 256;
                int d = idx >> 4, kc = idx & 15;
                int c = kc >> 3, f = kc & 7;
                float4 v = *(const float4*)(g_v + ((size_t)bh * DH + d) * SEQ + kt1 + c * 32 + f * 4);
                v.x = rna_tf32(v.x); v.y = rna_tf32(v.y);
                v.z = rna_tf32(v.z); v.w = rna_tf32(v.w);
                *(float4*)(smem + bufb + OFF_VT + c * 8192 + SWZ128((uint32_t)(d * 128 + f * 16))) = v;
            }
            if (tid < 64) {
                float* kp = (float*)(smem + ((cur ^ 1) ? SM_KEEP1 : SM_KEEP0));
                kp[tid] = (mask[b * SEQ + kt1 + tid] == 1) ? 1.f : 0.f;
            }
        }

        MBAR_WAIT(smem_base + SM_MBAR_S, t & 1);
        TC_FENCE_AFTER();
        {
            const float* keepf = (const float*)(smem + (cur ? SM_KEEP1 : SM_KEEP0));
            uint32_t sr[32];
            TC_LD_X32(sr, tmem + TSP + colbase);
            TC_WAIT_LD();
            uint32_t pr[32];
            #pragma unroll
            for (int r = 0; r < 32; r++) {
                float s = __uint_as_float(sr[r]);
                float p = keepf[colbase + r] * __expf(s);
                lsum += p;
                pr[r] = rna_tf32_bits(p);
            }
            TC_ST_X32(tmem + TSP + colbase + warpoff, pr);
        }
        TC_WAIT_ST();
        TC_FENCE_BEFORE();
        __syncthreads();

        if (wid == 0) {
            TC_FENCE_AFTER();
            if (elect_one()) {
                #pragma unroll
                for (int s = 0; s < 8; s++) {
                    uint64_t bd = MKDESC(smem_base + SM_BUF0 + cur * BUFSZ + OFF_VT
                                         + (s >> 2) * 8192) + 2 * (s & 3);
                    mma_tf32_ts(tmem + TTO, tmem + TSP + 8 * s, bd, IDESC_A,
                                !(t == 0 && s == 0));
                }
                TC_COMMIT(smem_base + SM_MBAR_PV);
            }
        }
    }

    MBAR_WAIT(smem_base + SM_MBAR_PV, 1);
    TC_FENCE_AFTER();

    float* lsums = (float*)(smem + SM_LSUM);
    lsums[tid] = lsum;
    __syncthreads();

    if (tid < 128) {
        const float ltot = lsums[tid] + lsums[tid + 128];
        uint32_t o0[32], o1[32];
        TC_LD_X32(o0, tmem + TTO);
        TC_LD_X32(o1, tmem + TTO + 32);
        TC_WAIT_LD();
        TC_FENCE_BEFORE();

        const int sq = q0 + tid;
        const float inv = (mask[b * SEQ + sq] == 1) ? (1.f / ltot) : 0.f;
        float* op = out + ((size_t)b * SEQ + sq) * EDIM + h * DH;
        #pragma unroll
        for (int i = 0; i < 8; i++) {
            float4 v;
            v.x = __uint_as_float(o0[i*4+0]) * inv;
            v.y = __uint_as_float(o0[i*4+1]) * inv;
            v.z = __uint_as_float(o0[i*4+2]) * inv;
            v.w = __uint_as_float(o0[i*4+3]) * inv;
            *(float4*)&op[i * 4] = v;
        }
        #pragma unroll
        for (int i = 0; i < 8; i++) {
            float4 v;
            v.x = __uint_as_float(o1[i*4+0]) * inv;
            v.y = __uint_as_float(o1[i*4+1]) * inv;
            v.z = __uint_as_float(o1[i*4+2]) * inv;
            v.w = __uint_as_float(o1[i*4+3]) * inv;
            *(float4*)&op[32 + i * 4] = v;
        }
    }

    __syncthreads();
    if (wid == 0) TC_DEALLOC(tmem, 256);

#else  // ---------------- fp32 fallback (non-'a' compile pass) ----------------
    float* ks    = (float*)smem;
    float* vs    = (float*)(smem + 16384);
    float* keepf = (float*)(smem + 32768);

    const int sq = q0 + (tid & 127);
    const float* qptr = g_q + ((size_t)bh * SEQ + sq) * DH;
    float q[DH];
    #pragma unroll
    for (int d = 0; d < DH; d++) q[d] = qptr[d] * 0.125f;
    float lsum = 0.f;
    float acc[DH];
    #pragma unroll
    for (int d = 0; d < DH; d++) acc[d] = 0.f;

    for (int kt0 = 0; kt0 < SEQ; kt0 += 64) {
        __syncthreads();
        const float4* kg = (const float4*)(g_k + ((size_t)bh * SEQ + kt0) * DH);
        #pragma unroll
        for (int i = 0; i < 4; i++) {
            int idx = tid + i * 256;
            ((float4*)ks)[idx] = kg[idx];
            int d = idx >> 4, f = idx & 15;
            float4 v = *(const float4*)(g_v + ((size_t)bh * DH + d) * SEQ + kt0 + f * 4);
            vs[(f*4+0)*64 + d] = v.x; vs[(f*4+1)*64 + d] = v.y;
            vs[(f*4+2)*64 + d] = v.z; vs[(f*4+3)*64 + d] = v.w;
        }
        if (tid < 64)
            keepf[tid] = (mask[b * SEQ + kt0 + tid] == 1) ? 1.f : 0.f;
        __syncthreads();

        if (tid < 128) {
            for (int j = 0; j < 64; j++) {
                const float* kr = ks + j * 64;
                float s = 0.f;
                #pragma unroll
                for (int d = 0; d < DH; d++) s += q[d] * kr[d];
                float p = keepf[j] * __expf(s);
                lsum += p;
                const float* vr = vs + j * 64;
                #pragma unroll
                for (int d = 0; d < DH; d++) acc[d] += p * vr[d];
            }
        }
    }
    if (tid < 128) {
        const float inv = (mask[b * SEQ + sq] == 1) ? (1.f / lsum) : 0.f;
        float* op = out + ((size_t)b * SEQ + sq) * EDIM + h * DH;
        #pragma unroll
        for (int d = 0; d < DH; d++) op[d] = acc[d] * inv;
    }
#endif
}

// ===========================================================================
extern "C" void kernel_launch(void* const* d_in, const int* in_sizes, int n_in,
                              void* d_out, int out_size)
{
    const float* x     = (const float*)d_in[0];
    const float* etype = (const float*)d_in[1];
    const int*   mask  = (const int*)  d_in[2];
    const float* Wq    = (const float*)d_in[3];
    const float* bq    = (const float*)d_in[4];
    const float* Wk    = (const float*)d_in[5];
    const float* bk    = (const float*)d_in[6];
    const float* Wv    = (const float*)d_in[7];
    const float* bv    = (const float*)d_in[8];
    float* out = (float*)d_out;

    static int smem_set = 0;
    if (!smem_set) {
        cudaFuncSetAttribute(tc_gemm, cudaFuncAttributeMaxDynamicSharedMemorySize, GT_TOTAL);
        cudaFuncSetAttribute(attn_tc, cudaFuncAttributeMaxDynamicSharedMemorySize, SM_TOTAL);
        smem_set = 1;
    }

    cvt_wt<<<dim3(16, 16, 3), 256>>>(Wq, Wk, Wv);

    dim3 ggrid(MROWS / 128, (3 * EDIM) / 64);    // 64 x 24
    tc_gemm<<<ggrid, 128, GT_TOTAL>>>(x, etype, bq, bk, bv);

    dim3 agrid(SEQ / 128, BATCH * HEADS);        // 16 x 32
    attn_tc<<<agrid, 256, SM_TOTAL>>>(mask, out);
}

// round 16
// speedup vs baseline: 1.3587x; 1.0039x over previous
#include <cuda_runtime.h>
#include <cuda_bf16.h>
#include <cstdint>

// Problem constants
#define BATCH 4
#define SEQ   2048
#define FDIM  512
#define EDIM  512
#define HEADS 8
#define DH    64
#define MROWS (BATCH*SEQ)      // 8192

// Q pre-scale: 1/sqrt(DH) * log2(e), so scores are in log2 domain -> exp2f.
#define QSCALE 0.18033688011112042f

// tcgen05 only exists in arch-accelerated ('a') compilation passes.
#if defined(__CUDA_ARCH_FEAT_SM103_ALL) || defined(__CUDA_ARCH_FEAT_SM100_ALL) || \
    defined(__CUDA_ARCH_SPECIFIC__) || defined(__CUDA_ARCH_FAMILY_SPECIFIC__)
#define TC_ENABLED 1
#else
#define TC_ENABLED 0
#endif

// Scratch: Q/K in [B,H,S,DH]; V stored TRANSPOSED [B,H,DH,S] (all fp32).
__device__ float g_q[(size_t)BATCH*HEADS*SEQ*DH];
__device__ float g_k[(size_t)BATCH*HEADS*SEQ*DH];
__device__ float g_v[(size_t)BATCH*HEADS*DH*SEQ];
// W^T concat [1536 n][512 k] fp32 (Wq^T | Wk^T | Wv^T), written by cvt_wt.
__device__ float g_wt[(size_t)3*EDIM*FDIM];

// ===========================================================================
// PTX helpers
// ===========================================================================
__device__ __forceinline__ uint32_t smem_u32(const void* p) {
    uint32_t a;
    asm("{ .reg .u64 t; cvta.to.shared.u64 t, %1; cvt.u32.u64 %0, t; }" : "=r"(a) : "l"(p));
    return a;
}
__device__ __forceinline__ bool elect_one() {
    uint32_t pred;
    asm volatile("{\n\t.reg .pred p;\n\telect.sync _|p, 0xFFFFFFFF;\n\t"
                 "selp.b32 %0, 1, 0, p;\n\t}" : "=r"(pred));
    return pred != 0;
}
__device__ __forceinline__ float rna_tf32(float x) {
    uint32_t u;
    asm("cvt.rna.tf32.f32 %0, %1;" : "=r"(u) : "f"(x));
    return __uint_as_float(u);
}
__device__ __forceinline__ uint32_t rna_tf32_bits(float x) {
    uint32_t u;
    asm("cvt.rna.tf32.f32 %0, %1;" : "=r"(u) : "f"(x));
    return u;
}
// bf16 hi/lo split of a pair (a=low half, b=high half)
__device__ __forceinline__ void bf16_split2(float a, float b, uint32_t& h, uint32_t& l) {
    __nv_bfloat16 ha = __float2bfloat16(a), hb = __float2bfloat16(b);
    float ra = a - __bfloat162float(ha);
    float rb = b - __bfloat162float(hb);
    __nv_bfloat16 la = __float2bfloat16(ra), lb = __float2bfloat16(rb);
    h = ((uint32_t)__bfloat16_as_ushort(hb) << 16) | __bfloat16_as_ushort(ha);
    l = ((uint32_t)__bfloat16_as_ushort(lb) << 16) | __bfloat16_as_ushort(la);
}

#define TC_ALLOC(smem_addr, n) \
    asm volatile("tcgen05.alloc.cta_group::1.sync.aligned.shared::cta.b32 [%0], %1;" \
                 :: "r"(smem_addr), "r"((uint32_t)(n)) : "memory")
#define TC_RELINQ() \
    asm volatile("tcgen05.relinquish_alloc_permit.cta_group::1.sync.aligned;")
#define TC_DEALLOC(tmem_addr, n) \
    asm volatile("tcgen05.dealloc.cta_group::1.sync.aligned.b32 %0, %1;" \
                 :: "r"(tmem_addr), "r"((uint32_t)(n)))
#define TC_WAIT_ST() asm volatile("tcgen05.wait::st.sync.aligned;" ::: "memory")
#define TC_WAIT_LD() asm volatile("tcgen05.wait::ld.sync.aligned;" ::: "memory")
#define TC_FENCE_BEFORE() asm volatile("tcgen05.fence::before_thread_sync;" ::: "memory")
#define TC_FENCE_AFTER()  asm volatile("tcgen05.fence::after_thread_sync;" ::: "memory")
#define TC_COMMIT(mbar) \
    asm volatile("tcgen05.commit.cta_group::1.mbarrier::arrive::one.shared::cluster.b64 [%0];" \
                 :: "r"((uint32_t)(mbar)) : "memory")

#define TC_ST_X32(tmem_addr, r) \
    asm volatile("tcgen05.st.sync.aligned.32x32b.x32.b32 [%0], " \
        "{%1, %2, %3, %4, %5, %6, %7, %8, %9, %10, %11, %12, %13, %14, %15, %16, " \
        " %17, %18, %19, %20, %21, %22, %23, %24, %25, %26, %27, %28, %29, %30, %31, %32};" \
        :: "r"(tmem_addr), \
           "r"((r)[0]),"r"((r)[1]),"r"((r)[2]),"r"((r)[3]),"r"((r)[4]),"r"((r)[5]),"r"((r)[6]),"r"((r)[7]), \
           "r"((r)[8]),"r"((r)[9]),"r"((r)[10]),"r"((r)[11]),"r"((r)[12]),"r"((r)[13]),"r"((r)[14]),"r"((r)[15]), \
           "r"((r)[16]),"r"((r)[17]),"r"((r)[18]),"r"((r)[19]),"r"((r)[20]),"r"((r)[21]),"r"((r)[22]),"r"((r)[23]), \
           "r"((r)[24]),"r"((r)[25]),"r"((r)[26]),"r"((r)[27]),"r"((r)[28]),"r"((r)[29]),"r"((r)[30]),"r"((r)[31]) \
        : "memory")

#define TC_LD_X32(r, tmem_addr) \
    asm volatile("tcgen05.ld.sync.aligned.32x32b.x32.b32 " \
        "{%0, %1, %2, %3, %4, %5, %6, %7, %8, %9, %10, %11, %12, %13, %14, %15, " \
        " %16, %17, %18, %19, %20, %21, %22, %23, %24, %25, %26, %27, %28, %29, %30, %31}, [%32];" \
        : "=r"((r)[0]),"=r"((r)[1]),"=r"((r)[2]),"=r"((r)[3]),"=r"((r)[4]),"=r"((r)[5]),"=r"((r)[6]),"=r"((r)[7]), \
          "=r"((r)[8]),"=r"((r)[9]),"=r"((r)[10]),"=r"((r)[11]),"=r"((r)[12]),"=r"((r)[13]),"=r"((r)[14]),"=r"((r)[15]), \
          "=r"((r)[16]),"=r"((r)[17]),"=r"((r)[18]),"=r"((r)[19]),"=r"((r)[20]),"=r"((r)[21]),"=r"((r)[22]),"=r"((r)[23]), \
          "=r"((r)[24]),"=r"((r)[25]),"=r"((r)[26]),"=r"((r)[27]),"=r"((r)[28]),"=r"((r)[29]),"=r"((r)[30]),"=r"((r)[31]) \
        : "r"(tmem_addr))

#define MBAR_INIT(mbar, cnt) \
    asm volatile("mbarrier.init.shared.b64 [%0], %1;" :: "r"((uint32_t)(mbar)), "r"((uint32_t)(cnt)) : "memory")

#define MBAR_WAIT(mbar, parity) do { \
    uint32_t _m = (uint32_t)(mbar); uint32_t _p = (uint32_t)(parity); uint32_t _done; \
    asm volatile("{\n\t.reg .pred p;\n\t" \
        "mbarrier.try_wait.parity.acquire.cta.shared::cta.b64 p, [%1], %2;\n\t" \
        "selp.b32 %0, 1, 0, p;\n\t}" : "=r"(_done) : "r"(_m), "r"(_p) : "memory"); \
    if (!_done) { \
        asm volatile("{\n\t.reg .pred P1;\n\t" \
            "WAIT_LOOP_%=:\n\t" \
            "mbarrier.try_wait.parity.acquire.cta.shared::cta.b64 P1, [%0], %1, 0x989680;\n\t" \
            "@P1 bra.uni WAIT_DONE_%=;\n\t" \
            "bra.uni WAIT_LOOP_%=;\n\t" \
            "WAIT_DONE_%=:\n\t}" :: "r"(_m), "r"(_p) : "memory"); \
    } \
} while (0)

// SW128 SMEM descriptor (layout=2, version=1, SBO=64, LBO=1)
#define SMEM_DESC_BASE_SW128 \
    ((uint64_t(2) << 61) | (uint64_t(1) << 46) | (uint64_t(64) << 32) | (uint64_t(1) << 16))
#define MKDESC(addr) (SMEM_DESC_BASE_SW128 | ((uint64_t)((addr) >> 4) & 0x3FFF))
#define SWZ128(o) ((o) ^ (((o) >> 3) & 0x70))

#if TC_ENABLED
__device__ __forceinline__ void mma_tf32_ts(uint32_t d, uint32_t a, uint64_t bdesc,
                                            uint32_t idesc, bool acc) {
    uint32_t e = acc ? 1u : 0u;
    asm volatile("{\n\t.reg .pred p;\n\tsetp.ne.u32 p, %4, 0;\n\t"
        "tcgen05.mma.cta_group::1.kind::tf32 [%0], [%1], %2, %3, p;\n\t}"
        :: "r"(d), "r"(a), "l"(bdesc), "r"(idesc), "r"(e) : "memory");
}
__device__ __forceinline__ void mma_f16_ts(uint32_t d, uint32_t a, uint64_t bdesc,
                                           uint32_t idesc, bool acc) {
    uint32_t e = acc ? 1u : 0u;
    asm volatile("{\n\t.reg .pred p;\n\tsetp.ne.u32 p, %5, 0;\n\t"
        "tcgen05.mma.cta_group::1.kind::f16 [%0], [%1], %2, %3, {%4, %4, %4, %4}, p;\n\t}"
        :: "r"(d), "r"(a), "l"(bdesc), "r"(idesc), "r"(0u), "r"(e) : "memory");
}
#endif

// tf32 idesc (attention, round-9 proven): M=128, N=64
#define IDESC_A ((1u<<4)|(2u<<7)|(2u<<10)|((64u/8)<<17)|((128u/16)<<24))
// bf16 idesc (GEMM, round-14 proven): M=128, N=64
#define IDESC_G ((1u<<4)|(1u<<7)|(1u<<10)|((64u/8)<<17)|((128u/16)<<24))

// ===========================================================================
// cvt_wt (proven, unchanged)
// ===========================================================================
__global__ __launch_bounds__(256)
void cvt_wt(const float* __restrict__ Wq, const float* __restrict__ Wk,
            const float* __restrict__ Wv)
{
    __shared__ float t[32][33];
    const int z = blockIdx.z;
    const float* W = (z == 0) ? Wq : (z == 1) ? Wk : Wv;
    const int k0 = blockIdx.x * 32;
    const int n0 = blockIdx.y * 32;
    const int tx = threadIdx.x & 31;
    const int ty = threadIdx.x >> 5;
    #pragma unroll
    for (int i = 0; i < 4; i++)
        t[ty + 8*i][tx] = W[(size_t)(k0 + ty + 8*i) * EDIM + n0 + tx];
    __syncthreads();
    #pragma unroll
    for (int i = 0; i < 4; i++)
        g_wt[(size_t)(z * EDIM + n0 + ty + 8*i) * FDIM + k0 + tx] = t[tx][ty + 8*i];
}

// ===========================================================================
// tcgen05 bf16x3 projection GEMM (round-14 PROVEN, byte-identical).
// TMEM: Xh[0..31], Xl[32..63] (bf16x2), D[64..127] fp32. Alloc 128 -> occ 4.
// ===========================================================================
#define TXH 0
#define TXL 32
#define TD  64
#define GT_TMEMPTR 0
#define GT_MBAR    16
#define GT_BIAS    64                  // 64 floats
#define GT_WH      1024                // W^T hi [64n x 64k bf16] SW128, 8KB
#define GT_WL      (GT_WH + 8192)
#define GT_TOTAL   (GT_WL + 8192)      // 17408

__global__ __launch_bounds__(128)
void tc_gemm(const float* __restrict__ x,
             const float* __restrict__ etype,
             const float* __restrict__ bq, const float* __restrict__ bk,
             const float* __restrict__ bv)
{
    extern __shared__ char sm[];
    const int tid = threadIdx.x;
    const int m0 = blockIdx.x * 128;
    const int n0g = blockIdx.y * 64;
    const int which = n0g >> 9;
    const int e0 = n0g & 511;
    const int hh = e0 >> 6;
    const float* bias = (which == 0) ? bq : (which == 1) ? bk : bv;

#if TC_ENABLED
    const uint32_t base = smem_u32(sm);
    const int wid = tid >> 5;
    const uint32_t warpoff = (uint32_t)wid << 21;

    if (wid == 0) { TC_ALLOC(base + GT_TMEMPTR, 128); TC_RELINQ(); }
    __syncthreads();
    uint32_t tmem;
    asm volatile("ld.shared.b32 %0, [%1];" : "=r"(tmem) : "r"(base + GT_TMEMPTR));
    if (tid == 0) MBAR_INIT(base + GT_MBAR, 1);
    if (tid < 64) ((float*)(sm + GT_BIAS))[tid] = bias[e0 + tid];
    __syncthreads();

    const uint64_t dWH = MKDESC(base + GT_WH);
    const uint64_t dWL = MKDESC(base + GT_WL);

    for (int c = 0; c < 8; c++) {
        const int k0 = c * 64;
        // --- Stage W^T tile [64n x 64k] bf16 hi/lo ---
        #pragma unroll
        for (int i = 0; i < 4; i++) {
            int idx = tid + i * 128;            // 512 units of 16B
            int r = idx >> 3, seg = idx & 7;
            const float* wp = &g_wt[(size_t)(n0g + r) * FDIM + k0 + seg * 8];
            float4 v0 = *(const float4*)wp;
            float4 v1 = *(const float4*)(wp + 4);
            uint4 hi, lo;
            bf16_split2(v0.x, v0.y, hi.x, lo.x);
            bf16_split2(v0.z, v0.w, hi.y, lo.y);
            bf16_split2(v1.x, v1.y, hi.z, lo.z);
            bf16_split2(v1.z, v1.w, hi.w, lo.w);
            uint32_t o = SWZ128((uint32_t)(r * 128 + seg * 16));
            *(uint4*)(sm + GT_WH + o) = hi;
            *(uint4*)(sm + GT_WL + o) = lo;
        }
        // --- x chunk -> TMEM bf16x2 hi/lo ---
        {
            const float4* xp = (const float4*)(x + (size_t)(m0 + tid) * FDIM + k0);
            uint32_t rh[32], rl[32];
            #pragma unroll
            for (int i = 0; i < 16; i++) {
                float4 v = xp[i];
                bf16_split2(v.x, v.y, rh[i*2+0], rl[i*2+0]);
                bf16_split2(v.z, v.w, rh[i*2+1], rl[i*2+1]);
            }
            TC_ST_X32(tmem + TXH + warpoff, rh);
            TC_ST_X32(tmem + TXL + warpoff, rl);
            TC_WAIT_ST();
        }
        TC_FENCE_BEFORE();
        __syncthreads();

        // --- D += Xh@Wh + Xl@Wh + Xh@Wl  (4 K-steps of K=16 bf16) ---
        if (wid == 0) {
            TC_FENCE_AFTER();
            if (elect_one()) {
                #pragma unroll
                for (int s = 0; s < 4; s++) {
                    mma_f16_ts(tmem + TD, tmem + TXH + 8 * s, dWH + 2 * s, IDESC_G,
                               !(c == 0 && s == 0));
                    mma_f16_ts(tmem + TD, tmem + TXL + 8 * s, dWH + 2 * s, IDESC_G, true);
                    mma_f16_ts(tmem + TD, tmem + TXH + 8 * s, dWL + 2 * s, IDESC_G, true);
                }
                TC_COMMIT(base + GT_MBAR);
            }
        }
        MBAR_WAIT(base + GT_MBAR, c & 1);
        TC_FENCE_AFTER();
        __syncthreads();
    }

    // --- Epilogue: thread tid = row m0+tid (round-8/14 proven) ---
    uint32_t d0[32], d1[32];
    TC_LD_X32(d0, tmem + TD);
    TC_LD_X32(d1, tmem + TD + 32);
    TC_WAIT_LD();
    TC_FENCE_BEFORE();

    const int bb = m0 >> 11;
    const int sidx = (m0 & 2047) + tid;
    const float* bs = (const float*)(sm + GT_BIAS);

    if (which != 2) {
        float* outbuf = (which == 0) ? g_q : g_k;
        float* rowp = outbuf + ((size_t)(bb * HEADS + hh) * SEQ + sidx) * DH;
        const float* ep = (which == 0)
            ? etype + (size_t)(m0 + tid) * EDIM + e0 : nullptr;
        #pragma unroll
        for (int n4 = 0; n4 < 16; n4++) {
            const uint32_t* dr = (n4 < 8) ? d0 : d1;
            int j = (n4 & 7) * 4;
            float4 v;
            v.x = __uint_as_float(dr[j+0]) + bs[n4*4+0];
            v.y = __uint_as_float(dr[j+1]) + bs[n4*4+1];
            v.z = __uint_as_float(dr[j+2]) + bs[n4*4+2];
            v.w = __uint_as_float(dr[j+3]) + bs[n4*4+3];
            if (which == 0) {
                float4 e4 = *(const float4*)&ep[n4*4];
                v.x += e4.x; v.y += e4.y; v.z += e4.z; v.w += e4.w;
            }
            *(float4*)&rowp[n4*4] = v;
        }
    } else {
        float* vb = g_v + ((size_t)(bb * HEADS + hh) * DH) * SEQ + sidx;
        #pragma unroll
        for (int n = 0; n < 32; n++)
            vb[(size_t)n * SEQ] = __uint_as_float(d0[n]) + bs[n];
        #pragma unroll
        for (int n = 0; n < 32; n++)
            vb[(size_t)(n + 32) * SEQ] = __uint_as_float(d1[n]) + bs[n + 32];
    }
    __syncthreads();
    if (wid == 0) TC_DEALLOC(tmem, 128);

#else  // ------------- fp32 fallback GEMM (non-'a' compile pass) -------------
    const int bb = m0 >> 11;
    const int sidx = (m0 & 2047) + tid;
    float acc[64];
    #pragma unroll
    for (int n = 0; n < 64; n++) acc[n] = 0.f;
    for (int k = 0; k < FDIM; k++) {
        float a = x[(size_t)(m0 + tid) * FDIM + k];
        #pragma unroll 16
        for (int n = 0; n < 64; n++)
            acc[n] += a * g_wt[(size_t)(n0g + n) * FDIM + k];
    }
    if (which != 2) {
        float* outbuf = (which == 0) ? g_q : g_k;
        float* rowp = outbuf + ((size_t)(bb * HEADS + hh) * SEQ + sidx) * DH;
        for (int n = 0; n < 64; n++) {
            float v = acc[n] + bias[e0 + n];
            if (which == 0) v += etype[(size_t)(m0 + tid) * EDIM + e0 + n];
            rowp[n] = v;
        }
    } else {
        float* vb = g_v + ((size_t)(bb * HEADS + hh) * DH) * SEQ + sidx;
        for (int n = 0; n < 64; n++)
            vb[(size_t)n * SEQ] = acc[n] + bias[e0 + n];
    }
#endif
}

// ===========================================================================
// tcgen05 tf32x3 attention — ROUND-9/14 PROVEN structure. Single change:
// Q pre-scale folds log2(e) so exp uses native exp2f (drops one FMUL per
// score element in the issue-bound exp section).
// TMEM: Qhi[0..63], Qlo[64..127], S/P in place [128..191], O [192..255].
// ===========================================================================
#define TQH 0
#define TQL 64
#define TSP 128
#define TTO 192
#define SM_TMEMPTR 0
#define SM_MBAR_S  16
#define SM_MBAR_PV 24
#define SM_KEEP0   64
#define SM_KEEP1   320
#define SM_LSUM    576
#define SM_BUF0    2048
#define BUFSZ      49152
#define OFF_KH0    0
#define OFF_KH1    8192
#define OFF_KL0    16384
#define OFF_KL1    24576
#define OFF_VT     32768
#define SM_TOTAL   (SM_BUF0 + 2*BUFSZ) // 100352

__global__ __launch_bounds__(256, 2)
void attn_tc(const int* __restrict__ mask, float* __restrict__ out)
{
    extern __shared__ char smem[];
    const int tid = threadIdx.x;
    const int bh = blockIdx.y, b = bh >> 3, h = bh & 7;
    const int q0 = blockIdx.x * 128;

#if TC_ENABLED
    const uint32_t smem_base = smem_u32(smem);
    const int wid = tid >> 5;
    const uint32_t warpoff = (uint32_t)(wid & 3) << 21;

    if (wid == 0) { TC_ALLOC(smem_base + SM_TMEMPTR, 256); TC_RELINQ(); }
    __syncthreads();
    uint32_t tmem;
    asm volatile("ld.shared.b32 %0, [%1];" : "=r"(tmem) : "r"(smem_base + SM_TMEMPTR));

    if (tid == 0) {
        MBAR_INIT(smem_base + SM_MBAR_S, 1);
        MBAR_INIT(smem_base + SM_MBAR_PV, 1);
    }

    // Q -> TMEM hi/lo (warps 0-3; thread tid = query row; 32-col passes)
    if (tid < 128) {
        const float4* qp = (const float4*)(g_q + ((size_t)bh * SEQ + q0 + tid) * DH);
        #pragma unroll
        for (int half = 0; half < 2; half++) {
            uint32_t rh[32], rl[32];
            #pragma unroll
            for (int i = 0; i < 8; i++) {
                float4 v = qp[half * 8 + i];
                float f[4] = { v.x * QSCALE, v.y * QSCALE, v.z * QSCALE, v.w * QSCALE };
                #pragma unroll
                for (int c = 0; c < 4; c++) {
                    float hi = rna_tf32(f[c]);
                    rh[i*4+c] = __float_as_uint(hi);
                    rl[i*4+c] = rna_tf32_bits(f[c] - hi);
                }
            }
            TC_ST_X32(tmem + TQH + half * 32 + warpoff, rh);
            TC_ST_X32(tmem + TQL + half * 32 + warpoff, rl);
        }
        TC_WAIT_ST();
        TC_FENCE_BEFORE();
    }

    // Stage tile 0 into buffer 0 (all 256 threads)
    {
        const uint32_t bufb = SM_BUF0;
        const float4* kg = (const float4*)(g_k + (size_t)bh * SEQ * DH);
        #pragma unroll
        for (int i = 0; i < 4; i++) {
            int idx = tid + i * 256;
            int r = idx >> 4, c4 = idx & 15;
            float4 v = kg[idx];
            float4 hi, lo;
            hi.x = rna_tf32(v.x); lo.x = rna_tf32(v.x - hi.x);
            hi.y = rna_tf32(v.y); lo.y = rna_tf32(v.y - hi.y);
            hi.z = rna_tf32(v.z); lo.z = rna_tf32(v.z - hi.z);
            hi.w = rna_tf32(v.w); lo.w = rna_tf32(v.w - hi.w);
            uint32_t o = SWZ128((uint32_t)(r * 128 + (c4 & 7) * 16));
            uint32_t hsel = (c4 & 8) ? 8192u : 0u;
            *(float4*)(smem + bufb + OFF_KH0 + hsel + o) = hi;
            *(float4*)(smem + bufb + OFF_KL0 + hsel + o) = lo;
        }
        #pragma unroll
        for (int i = 0; i < 4; i++) {
            int idx = tid + i * 256;
            int d = idx >> 4, kc = idx & 15;
            int c = kc >> 3, f = kc & 7;
            float4 v = *(const float4*)(g_v + ((size_t)bh * DH + d) * SEQ + c * 32 + f * 4);
            v.x = rna_tf32(v.x); v.y = rna_tf32(v.y);
            v.z = rna_tf32(v.z); v.w = rna_tf32(v.w);
            *(float4*)(smem + bufb + OFF_VT + c * 8192 + SWZ128((uint32_t)(d * 128 + f * 16))) = v;
        }
        if (tid < 64)
            ((float*)(smem + SM_KEEP0))[tid] = (mask[b * SEQ + tid] == 1) ? 1.f : 0.f;
    }
    __syncthreads();

    uint64_t dKH0[2], dKH1[2], dKL0[2], dKL1[2];
    #pragma unroll
    for (int bf = 0; bf < 2; bf++) {
        uint32_t bb2 = smem_base + SM_BUF0 + bf * BUFSZ;
        dKH0[bf] = MKDESC(bb2 + OFF_KH0);
        dKH1[bf] = MKDESC(bb2 + OFF_KH1);
        dKL0[bf] = MKDESC(bb2 + OFF_KL0);
        dKL1[bf] = MKDESC(bb2 + OFF_KL1);
    }

    float lsum = 0.f;
    const int colbase = (wid >> 2) * 32;

    for (int t = 0; t < 32; t++) {
        const int cur = t & 1;
        if (t > 0) MBAR_WAIT(smem_base + SM_MBAR_PV, (t - 1) & 1);

        if (wid == 0) {
            TC_FENCE_AFTER();
            if (elect_one()) {
                #pragma unroll
                for (int s = 0; s < 8; s++) {
                    uint64_t bh_d = (s < 4) ? (dKH0[cur] + 2 * s) : (dKH1[cur] + 2 * (s - 4));
                    uint64_t bl_d = (s < 4) ? (dKL0[cur] + 2 * s) : (dKL1[cur] + 2 * (s - 4));
                    mma_tf32_ts(tmem + TSP, tmem + TQH + 8 * s, bh_d, IDESC_A, s > 0);
                    mma_tf32_ts(tmem + TSP, tmem + TQL + 8 * s, bh_d, IDESC_A, true);
                    mma_tf32_ts(tmem + TSP, tmem + TQH + 8 * s, bl_d, IDESC_A, true);
                }
                TC_COMMIT(smem_base + SM_MBAR_S);
            }
        }

        if (t < 31) {
            const int kt1 = (t + 1) * 64;
            const uint32_t bufb = SM_BUF0 + (cur ^ 1) * BUFSZ;
            const float4* kg = (const float4*)(g_k + ((size_t)bh * SEQ + kt1) * DH);
            #pragma unroll
            for (int i = 0; i < 4; i++) {
                int idx = tid + i * 256;
                int r = idx >> 4, c4 = idx & 15;
                float4 v = kg[idx];
                float4 hi, lo;
                hi.x = rna_tf32(v.x); lo.x = rna_tf32(v.x - hi.x);
                hi.y = rna_tf32(v.y); lo.y = rna_tf32(v.y - hi.y);
                hi.z = rna_tf32(v.z); lo.z = rna_tf32(v.z - hi.z);
                hi.w = rna_tf32(v.w); lo.w = rna_tf32(v.w - hi.w);
                uint32_t o = SWZ128((uint32_t)(r * 128 + (c4 & 7) * 16));
                uint32_t hsel = (c4 & 8) ? 8192u : 0u;
                *(float4*)(smem + bufb + OFF_KH0 + hsel + o) = hi;
                *(float4*)(smem + bufb + OFF_KL0 + hsel + o) = lo;
            }
            #pragma unroll
            for (int i = 0; i < 4; i++) {
                int idx = tid + i * 256;
                int d = idx >> 4, kc = idx & 15;
                int c = kc >> 3, f = kc & 7;
                float4 v = *(const float4*)(g_v + ((size_t)bh * DH + d) * SEQ + kt1 + c * 32 + f * 4);
                v.x = rna_tf32(v.x); v.y = rna_tf32(v.y);
                v.z = rna_tf32(v.z); v.w = rna_tf32(v.w);
                *(float4*)(smem + bufb + OFF_VT + c * 8192 + SWZ128((uint32_t)(d * 128 + f * 16))) = v;
            }
            if (tid < 64) {
                float* kp = (float*)(smem + ((cur ^ 1) ? SM_KEEP1 : SM_KEEP0));
                kp[tid] = (mask[b * SEQ + kt1 + tid] == 1) ? 1.f : 0.f;
            }
        }

        MBAR_WAIT(smem_base + SM_MBAR_S, t & 1);
        TC_FENCE_AFTER();
        {
            const float* keepf = (const float*)(smem + (cur ? SM_KEEP1 : SM_KEEP0));
            uint32_t sr[32];
            TC_LD_X32(sr, tmem + TSP + colbase);
            TC_WAIT_LD();
            uint32_t pr[32];
            #pragma unroll
            for (int r = 0; r < 32; r++) {
                float s = __uint_as_float(sr[r]);
                float p = keepf[colbase + r] * exp2f(s);   // Q pre-scaled by log2e
                lsum += p;
                pr[r] = rna_tf32_bits(p);
            }
            TC_ST_X32(tmem + TSP + colbase + warpoff, pr);
        }
        TC_WAIT_ST();
        TC_FENCE_BEFORE();
        __syncthreads();

        if (wid == 0) {
            TC_FENCE_AFTER();
            if (elect_one()) {
                #pragma unroll
                for (int s = 0; s < 8; s++) {
                    uint64_t bd = MKDESC(smem_base + SM_BUF0 + cur * BUFSZ + OFF_VT
                                         + (s >> 2) * 8192) + 2 * (s & 3);
                    mma_tf32_ts(tmem + TTO, tmem + TSP + 8 * s, bd, IDESC_A,
                                !(t == 0 && s == 0));
                }
                TC_COMMIT(smem_base + SM_MBAR_PV);
            }
        }
    }

    MBAR_WAIT(smem_base + SM_MBAR_PV, 1);
    TC_FENCE_AFTER();

    float* lsums = (float*)(smem + SM_LSUM);
    lsums[tid] = lsum;
    __syncthreads();

    if (tid < 128) {
        const float ltot = lsums[tid] + lsums[tid + 128];
        uint32_t o0[32], o1[32];
        TC_LD_X32(o0, tmem + TTO);
        TC_LD_X32(o1, tmem + TTO + 32);
        TC_WAIT_LD();
        TC_FENCE_BEFORE();

        const int sq = q0 + tid;
        const float inv = (mask[b * SEQ + sq] == 1) ? (1.f / ltot) : 0.f;
        float* op = out + ((size_t)b * SEQ + sq) * EDIM + h * DH;
        #pragma unroll
        for (int i = 0; i < 8; i++) {
            float4 v;
            v.x = __uint_as_float(o0[i*4+0]) * inv;
            v.y = __uint_as_float(o0[i*4+1]) * inv;
            v.z = __uint_as_float(o0[i*4+2]) * inv;
            v.w = __uint_as_float(o0[i*4+3]) * inv;
            *(float4*)&op[i * 4] = v;
        }
        #pragma unroll
        for (int i = 0; i < 8; i++) {
            float4 v;
            v.x = __uint_as_float(o1[i*4+0]) * inv;
            v.y = __uint_as_float(o1[i*4+1]) * inv;
            v.z = __uint_as_float(o1[i*4+2]) * inv;
            v.w = __uint_as_float(o1[i*4+3]) * inv;
            *(float4*)&op[32 + i * 4] = v;
        }
    }

    __syncthreads();
    if (wid == 0) TC_DEALLOC(tmem, 256);

#else  // ---------------- fp32 fallback (non-'a' compile pass) ----------------
    float* ks    = (float*)smem;
    float* vs    = (float*)(smem + 16384);
    float* keepf = (float*)(smem + 32768);

    const int sq = q0 + (tid & 127);
    const float* qptr = g_q + ((size_t)bh * SEQ + sq) * DH;
    float q[DH];
    #pragma unroll
    for (int d = 0; d < DH; d++) q[d] = qptr[d] * QSCALE;
    float lsum = 0.f;
    float acc[DH];
    #pragma unroll
    for (int d = 0; d < DH; d++) acc[d] = 0.f;

    for (int kt0 = 0; kt0 < SEQ; kt0 += 64) {
        __syncthreads();
        const float4* kg = (const float4*)(g_k + ((size_t)bh * SEQ + kt0) * DH);
        #pragma unroll
        for (int i = 0; i < 4; i++) {
            int idx = tid + i * 256;
            ((float4*)ks)[idx] = kg[idx];
            int d = idx >> 4, f = idx & 15;
            float4 v = *(const float4*)(g_v + ((size_t)bh * DH + d) * SEQ + kt0 + f * 4);
            vs[(f*4+0)*64 + d] = v.x; vs[(f*4+1)*64 + d] = v.y;
            vs[(f*4+2)*64 + d] = v.z; vs[(f*4+3)*64 + d] = v.w;
        }
        if (tid < 64)
            keepf[tid] = (mask[b * SEQ + kt0 + tid] == 1) ? 1.f : 0.f;
        __syncthreads();

        if (tid < 128) {
            for (int j = 0; j < 64; j++) {
                const float* kr = ks + j * 64;
                float s = 0.f;
                #pragma unroll
                for (int d = 0; d < DH; d++) s += q[d] * kr[d];
                float p = keepf[j] * exp2f(s);
                lsum += p;
                const float* vr = vs + j * 64;
                #pragma unroll
                for (int d = 0; d < DH; d++) acc[d] += p * vr[d];
            }
        }
    }
    if (tid < 128) {
        const float inv = (mask[b * SEQ + sq] == 1) ? (1.f / lsum) : 0.f;
        float* op = out + ((size_t)b * SEQ + sq) * EDIM + h * DH;
        #pragma unroll
        for (int d = 0; d < DH; d++) op[d] = acc[d] * inv;
    }
#endif
}

// ===========================================================================
extern "C" void kernel_launch(void* const* d_in, const int* in_sizes, int n_in,
                              void* d_out, int out_size)
{
    const float* x     = (const float*)d_in[0];
    const float* etype = (const float*)d_in[1];
    const int*   mask  = (const int*)  d_in[2];
    const float* Wq    = (const float*)d_in[3];
    const float* bq    = (const float*)d_in[4];
    const float* Wk    = (const float*)d_in[5];
    const float* bk    = (const float*)d_in[6];
    const float* Wv    = (const float*)d_in[7];
    const float* bv    = (const float*)d_in[8];
    float* out = (float*)d_out;

    static int smem_set = 0;
    if (!smem_set) {
        cudaFuncSetAttribute(tc_gemm, cudaFuncAttributeMaxDynamicSharedMemorySize, GT_TOTAL);
        cudaFuncSetAttribute(attn_tc, cudaFuncAttributeMaxDynamicSharedMemorySize, SM_TOTAL);
        smem_set = 1;
    }

    cvt_wt<<<dim3(16, 16, 3), 256>>>(Wq, Wk, Wv);

    dim3 ggrid(MROWS / 128, (3 * EDIM) / 64);    // 64 x 24
    tc_gemm<<<ggrid, 128, GT_TOTAL>>>(x, etype, bq, bk, bv);

    dim3 agrid(SEQ / 128, BATCH * HEADS);        // 16 x 32
    attn_tc<<<agrid, 256, SM_TOTAL>>>(mask, out);
}